// round 2
// baseline (speedup 1.0000x reference)
#include <cuda_runtime.h>
#include <cstdint>

#define NTOK 16384
#define DDIM 1024
#define HDIM 2048
#define NEXP 16
#define KTOP 2
#define CAP  2560

// ---------------- scratch (device globals; no allocation) ----------------
__device__ float g_ubuf[(size_t)NEXP * CAP * HDIM];   // 335 MB (also reused by shared path)
__device__ float g_act [(size_t)NEXP * CAP * HDIM];   // 335 MB
__device__ int   g_topi[NTOK * KTOP];
__device__ float g_wts [NTOK * KTOP];
__device__ int   g_cnt [NEXP];
__device__ int   g_tokl[NEXP * NTOK];
__device__ float g_wl  [NEXP * NTOK];
__device__ int   g_ktok[NEXP * CAP];
__device__ float g_kw  [NEXP * CAP];
__device__ int   g_mk  [NEXP];

// ---------------- gate: exact fp32 ----------------
__global__ void gate_kernel(const float* __restrict__ x, const float* __restrict__ gw,
                            const float* __restrict__ gb,
                            int* __restrict__ topi, float* __restrict__ wts) {
    int t = (blockIdx.x * blockDim.x + threadIdx.x) >> 5;
    int lane = threadIdx.x & 31;
    if (t >= NTOK) return;
    const float* xr = x + (size_t)t * DDIM;
    float s[NEXP];
#pragma unroll
    for (int e = 0; e < NEXP; e++) s[e] = 0.f;
    for (int i = lane; i < DDIM; i += 32) {
        float xv = xr[i];
        const float4* w4 = reinterpret_cast<const float4*>(gw + (size_t)i * NEXP);
#pragma unroll
        for (int q = 0; q < 4; q++) {
            float4 w = w4[q];
            s[q*4+0] += xv * w.x;
            s[q*4+1] += xv * w.y;
            s[q*4+2] += xv * w.z;
            s[q*4+3] += xv * w.w;
        }
    }
#pragma unroll
    for (int e = 0; e < NEXP; e++) {
#pragma unroll
        for (int off = 16; off > 0; off >>= 1)
            s[e] += __shfl_xor_sync(0xffffffffu, s[e], off);
    }
    if (lane == 0) {
        float mx = s[0];
#pragma unroll
        for (int e = 1; e < NEXP; e++) mx = fmaxf(mx, s[e]);
        float sum = 0.f, sc[NEXP];
#pragma unroll
        for (int e = 0; e < NEXP; e++) { sc[e] = expf(s[e] - mx); sum += sc[e]; }
        float inv = 1.f / sum;
#pragma unroll
        for (int e = 0; e < NEXP; e++) sc[e] = sc[e] * inv + gb[e];
        int i0 = 0; float v0 = sc[0];
#pragma unroll
        for (int e = 1; e < NEXP; e++) if (sc[e] > v0) { v0 = sc[e]; i0 = e; }
        int i1 = 0; float v1 = -1e30f;
#pragma unroll
        for (int e = 0; e < NEXP; e++) if (e != i0 && sc[e] > v1) { v1 = sc[e]; i1 = e; }
        topi[t*2+0] = i0; topi[t*2+1] = i1;
        wts [t*2+0] = s[i0]; wts[t*2+1] = s[i1];   // weights = raw logits (ROUTE_SCALE=1)
    }
}

// ---------------- assignment lists ----------------
__global__ void assign_kernel(const int* __restrict__ topi, const float* __restrict__ wts,
                              int* __restrict__ cnt, int* __restrict__ tokl,
                              float* __restrict__ wl) {
    int i = blockIdx.x * blockDim.x + threadIdx.x;
    if (i >= NTOK * KTOP) return;
    int e = topi[i];
    int p = atomicAdd(&cnt[e], 1);
    tokl[(size_t)e * NTOK + p] = i >> 1;
    wl  [(size_t)e * NTOK + p] = wts[i];
}

__device__ __forceinline__ unsigned fkey(float f) {
    unsigned u = __float_as_uint(f);
    return (u & 0x80000000u) ? ~u : (u | 0x80000000u);
}

// ---------------- per-expert capacity selection (exact, matches lax.top_k ties) ----------------
__global__ void select_kernel(const int* __restrict__ cnt, const int* __restrict__ tokl,
                              const float* __restrict__ wl,
                              int* __restrict__ ktok, float* __restrict__ kw,
                              int* __restrict__ mk) {
    int e = blockIdx.x;
    int n = cnt[e];
    const int*   tl = tokl + (size_t)e * NTOK;
    const float* wv = wl   + (size_t)e * NTOK;
    int tid = threadIdx.x;

    if (n <= CAP) {
        for (int i = tid; i < n; i += blockDim.x) {
            ktok[(size_t)e * CAP + i] = tl[i];
            kw  [(size_t)e * CAP + i] = wv[i];
        }
        if (tid == 0) mk[e] = n;
        return;
    }

    __shared__ int hist[256];
    __shared__ unsigned s_prefix;
    __shared__ int s_rem, s_nk, s_neq;
    __shared__ int eq_tok[2048];
    __shared__ int eq_src[2048];
    if (tid == 0) { s_prefix = 0u; s_rem = CAP; }
    __syncthreads();

    for (int shift = 24; shift >= 0; shift -= 8) {
        for (int b = tid; b < 256; b += blockDim.x) hist[b] = 0;
        __syncthreads();
        unsigned pfx = s_prefix;
        for (int i = tid; i < n; i += blockDim.x) {
            unsigned key = fkey(wv[i]);
            if (shift == 24 || (key >> (shift + 8)) == pfx)
                atomicAdd(&hist[(key >> shift) & 255], 1);
        }
        __syncthreads();
        if (tid == 0) {
            int rem = s_rem;
            int b = 255;
            for (; b > 0; b--) { if (hist[b] >= rem) break; rem -= hist[b]; }
            s_prefix = (pfx << 8) | (unsigned)b;
            s_rem = rem;
        }
        __syncthreads();
    }
    unsigned T = s_prefix;
    int rem = s_rem;
    if (tid == 0) { s_nk = 0; s_neq = 0; }
    __syncthreads();
    for (int i = tid; i < n; i += blockDim.x) {
        unsigned key = fkey(wv[i]);
        if (key > T) {
            int p = atomicAdd(&s_nk, 1);
            ktok[(size_t)e * CAP + p] = tl[i];
            kw  [(size_t)e * CAP + p] = wv[i];
        } else if (key == T) {
            int p = atomicAdd(&s_neq, 1);
            if (p < 2048) { eq_tok[p] = tl[i]; eq_src[p] = i; }
        }
    }
    __syncthreads();
    int neq = min(s_neq, 2048);
    // among equal-weight entries, keep 'rem' with smallest token index (lax.top_k tie rule)
    for (int j = tid; j < neq; j += blockDim.x) {
        int tj = eq_tok[j];
        int rank = 0;
        for (int l = 0; l < neq; l++) rank += (eq_tok[l] < tj);
        if (rank < rem) {
            int p = atomicAdd(&s_nk, 1);
            ktok[(size_t)e * CAP + p] = tj;
            kw  [(size_t)e * CAP + p] = wv[eq_src[j]];
        }
    }
    __syncthreads();
    if (tid == 0) mk[e] = s_nk;
}

// ---------------- TF32 tensor-core GEMM ----------------
// C[M,N] = A[M,K] @ B[K,N]  (B row-major, ldb=N).  Tiles 128x128x32, 8 warps, m16n8k8.tf32.
// MODE 0: C=acc   MODE 1: C=silu(acc)*U   MODE 4: atomicAdd(C[gidx? gidx[r]:r], acc*roww[r]*outscale)
__device__ __forceinline__ unsigned cvt_tf32(float f) {
    unsigned r; asm("cvt.rna.tf32.f32 %0, %1;" : "=r"(r) : "f"(f)); return r;
}

template<int MODE, bool GATHER>
__global__ void __launch_bounds__(256, 2)
gemm_tf32(const float* __restrict__ A, size_t sAz, int lda,
          const float* __restrict__ B, size_t sBz,
          float* __restrict__ C, size_t sCz, int ldc,
          const float* __restrict__ U, size_t sUz,
          const int* __restrict__ mlist, int Mmax,
          int N, int K,
          const int* __restrict__ gidx, size_t sGz,
          const float* __restrict__ roww, size_t sWz,
          float outscale)
{
    int z = blockIdx.z;
    int M = mlist ? mlist[z] : Mmax;
    int row0 = blockIdx.y * 128;
    if (row0 >= M) return;
    int col0 = blockIdx.x * 128;

    A += sAz * z; B += sBz * z; C += sCz * z;
    if (MODE == 1) U += sUz * z;
    const int*   gl = gidx ? gidx + sGz * z : nullptr;
    const float* rw = roww ? roww + sWz * z : nullptr;

    __shared__ unsigned As[128][36];   // [m][k], pad 4 -> conflict-free frag loads
    __shared__ unsigned Bs[32][136];   // [k][n], pad 8 -> conflict-free frag loads

    int tid  = threadIdx.x;
    int lane = tid & 31;
    int wid  = tid >> 5;
    int wm   = wid >> 1;    // 0..3 -> 32 rows each
    int wn   = wid & 1;     // 0..1 -> 64 cols each

    float acc[2][8][4];
#pragma unroll
    for (int mt = 0; mt < 2; mt++)
#pragma unroll
        for (int nt = 0; nt < 8; nt++)
#pragma unroll
            for (int q = 0; q < 4; q++) acc[mt][nt][q] = 0.f;

    int ar = tid >> 3;            // 0..31
    int ak = (tid & 7) * 4;       // 0,4,...,28
    int bkp = tid >> 5;           // 0..7
    int bn  = (tid & 31) * 4;     // 0..124

    int growv[4];
#pragma unroll
    for (int p = 0; p < 4; p++) {
        int gr = row0 + p * 32 + ar;
        growv[p] = (gr < M) ? (GATHER ? gl[gr] : gr) : -1;
    }

    for (int kb = 0; kb < K; kb += 32) {
#pragma unroll
        for (int p = 0; p < 4; p++) {
            int r = p * 32 + ar;
            float4 v = make_float4(0.f, 0.f, 0.f, 0.f);
            int gr = growv[p];
            if (gr >= 0) v = *reinterpret_cast<const float4*>(A + (size_t)gr * lda + kb + ak);
            As[r][ak+0] = cvt_tf32(v.x);
            As[r][ak+1] = cvt_tf32(v.y);
            As[r][ak+2] = cvt_tf32(v.z);
            As[r][ak+3] = cvt_tf32(v.w);
        }
#pragma unroll
        for (int p = 0; p < 4; p++) {
            int k = p * 8 + bkp;
            float4 v = *reinterpret_cast<const float4*>(B + (size_t)(kb + k) * N + col0 + bn);
            Bs[k][bn+0] = cvt_tf32(v.x);
            Bs[k][bn+1] = cvt_tf32(v.y);
            Bs[k][bn+2] = cvt_tf32(v.z);
            Bs[k][bn+3] = cvt_tf32(v.w);
        }
        __syncthreads();

#pragma unroll
        for (int ks = 0; ks < 4; ks++) {
            int kk = ks * 8;
            unsigned af[2][4], bf[8][2];
#pragma unroll
            for (int mt = 0; mt < 2; mt++) {
                int rb = wm * 32 + mt * 16 + (lane >> 2);
                int kc = kk + (lane & 3);
                af[mt][0] = As[rb    ][kc    ];
                af[mt][1] = As[rb + 8][kc    ];
                af[mt][2] = As[rb    ][kc + 4];
                af[mt][3] = As[rb + 8][kc + 4];
            }
#pragma unroll
            for (int nt = 0; nt < 8; nt++) {
                int nb = wn * 64 + nt * 8 + (lane >> 2);
                bf[nt][0] = Bs[kk + (lane & 3)    ][nb];
                bf[nt][1] = Bs[kk + (lane & 3) + 4][nb];
            }
#pragma unroll
            for (int mt = 0; mt < 2; mt++)
#pragma unroll
                for (int nt = 0; nt < 8; nt++) {
                    asm("mma.sync.aligned.m16n8k8.row.col.f32.tf32.tf32.f32 "
                        "{%0,%1,%2,%3}, {%4,%5,%6,%7}, {%8,%9}, {%0,%1,%2,%3};\n"
                        : "+f"(acc[mt][nt][0]), "+f"(acc[mt][nt][1]),
                          "+f"(acc[mt][nt][2]), "+f"(acc[mt][nt][3])
                        : "r"(af[mt][0]), "r"(af[mt][1]), "r"(af[mt][2]), "r"(af[mt][3]),
                          "r"(bf[nt][0]), "r"(bf[nt][1]));
                }
        }
        __syncthreads();
    }

    // epilogue
#pragma unroll
    for (int mt = 0; mt < 2; mt++) {
        int rbase = row0 + wm * 32 + mt * 16 + (lane >> 2);
#pragma unroll
        for (int nt = 0; nt < 8; nt++) {
            int cbase = col0 + wn * 64 + nt * 8 + (lane & 3) * 2;
#pragma unroll
            for (int q = 0; q < 4; q++) {
                int r = rbase + ((q >= 2) ? 8 : 0);
                int c = cbase + (q & 1);
                if (r < M) {
                    float v = acc[mt][nt][q];
                    if (MODE == 0) {
                        C[(size_t)r * ldc + c] = v;
                    } else if (MODE == 1) {
                        float sig = 1.f / (1.f + __expf(-v));
                        size_t off = (size_t)r * ldc + c;
                        C[off] = v * sig * U[off];
                    } else { // MODE 4
                        int ro = gl ? gl[r] : r;
                        float scl = (rw ? rw[r] : 1.f) * outscale;
                        atomicAdd(&C[(size_t)ro * ldc + c], v * scl);
                    }
                }
            }
        }
    }
}

// ---------------- host launcher ----------------
extern "C" void kernel_launch(void* const* d_in, const int* in_sizes, int n_in,
                              void* d_out, int out_size) {
    const float* x   = (const float*)d_in[0];
    const float* gw  = (const float*)d_in[1];
    const float* gb  = (const float*)d_in[2];
    const float* ew1 = (const float*)d_in[3];
    const float* ew3 = (const float*)d_in[4];
    const float* ew2 = (const float*)d_in[5];
    const float* sw1 = (const float*)d_in[6];
    const float* sw3 = (const float*)d_in[7];
    const float* sw2 = (const float*)d_in[8];
    float* out = (float*)d_out;

    float *ubuf, *act, *wts, *wl, *kw;
    int *topi, *cnt, *tokl, *ktok, *mk;
    cudaGetSymbolAddress((void**)&ubuf, g_ubuf);
    cudaGetSymbolAddress((void**)&act,  g_act);
    cudaGetSymbolAddress((void**)&topi, g_topi);
    cudaGetSymbolAddress((void**)&wts,  g_wts);
    cudaGetSymbolAddress((void**)&cnt,  g_cnt);
    cudaGetSymbolAddress((void**)&tokl, g_tokl);
    cudaGetSymbolAddress((void**)&wl,   g_wl);
    cudaGetSymbolAddress((void**)&ktok, g_ktok);
    cudaGetSymbolAddress((void**)&kw,   g_kw);
    cudaGetSymbolAddress((void**)&mk,   g_mk);

    cudaMemsetAsync(out, 0, (size_t)out_size * sizeof(float), 0);
    cudaMemsetAsync(cnt, 0, NEXP * sizeof(int), 0);

    gate_kernel<<<NTOK / 8, 256>>>(x, gw, gb, topi, wts);
    assign_kernel<<<(NTOK * KTOP + 255) / 256, 256>>>(topi, wts, cnt, tokl, wl);
    select_kernel<<<NEXP, 256>>>(cnt, tokl, wl, ktok, kw, mk);

    dim3 blk(256);

    // ---- shared experts (batched z=2), contribute 0.5 * swiglu(x) each ----
    gemm_tf32<0, false><<<dim3(HDIM/128, NTOK/128, 2), blk>>>(
        x, 0, DDIM, sw3, (size_t)DDIM * HDIM, ubuf, (size_t)NTOK * HDIM, HDIM,
        nullptr, 0, nullptr, NTOK, HDIM, DDIM, nullptr, 0, nullptr, 0, 1.f);
    gemm_tf32<1, false><<<dim3(HDIM/128, NTOK/128, 2), blk>>>(
        x, 0, DDIM, sw1, (size_t)DDIM * HDIM, act, (size_t)NTOK * HDIM, HDIM,
        ubuf, (size_t)NTOK * HDIM, nullptr, NTOK, HDIM, DDIM, nullptr, 0, nullptr, 0, 1.f);
    gemm_tf32<4, false><<<dim3(DDIM/128, NTOK/128, 2), blk>>>(
        act, (size_t)NTOK * HDIM, HDIM, sw2, (size_t)HDIM * DDIM, out, 0, DDIM,
        nullptr, 0, nullptr, NTOK, DDIM, HDIM, nullptr, 0, nullptr, 0, 0.5f);

    // ---- routed experts (batched z=16, gathered rows, capacity-dropped) ----
    gemm_tf32<0, true><<<dim3(HDIM/128, CAP/128, NEXP), blk>>>(
        x, 0, DDIM, ew3, (size_t)DDIM * HDIM, ubuf, (size_t)CAP * HDIM, HDIM,
        nullptr, 0, mk, CAP, HDIM, DDIM, ktok, CAP, nullptr, 0, 1.f);
    gemm_tf32<1, true><<<dim3(HDIM/128, CAP/128, NEXP), blk>>>(
        x, 0, DDIM, ew1, (size_t)DDIM * HDIM, act, (size_t)CAP * HDIM, HDIM,
        ubuf, (size_t)CAP * HDIM, mk, CAP, HDIM, DDIM, ktok, CAP, nullptr, 0, 1.f);
    gemm_tf32<4, false><<<dim3(DDIM/128, CAP/128, NEXP), blk>>>(
        act, (size_t)CAP * HDIM, HDIM, ew2, (size_t)HDIM * DDIM, out, 0, DDIM,
        nullptr, 0, mk, CAP, DDIM, HDIM, ktok, CAP, kw, CAP, 1.f);
}

// round 4
// speedup vs baseline: 1.2909x; 1.2909x over previous
#include <cuda_runtime.h>
#include <cuda_fp16.h>
#include <cstdint>

#define NTOK 16384
#define DDIM 1024
#define HDIM 2048
#define NEXP 16
#define CAP  2560
#define BM 128
#define BN 256
#define KC 64
#define PADK 72                      // halves per smem row (64 data + 8 pad)
#define A_BYTES (BM * PADK * 2)      // 18432
#define B_BYTES (BN * PADK * 2)      // 36864
#define BUF_BYTES (A_BYTES + B_BYTES)
#define SMEM_BYTES (2 * BUF_BYTES)   // 110592

// ---------------- scratch (device globals; no allocation) ----------------
__device__ __half g_ubuf[(size_t)NEXP * CAP * HDIM];   // u staging; later reused for y
__device__ __half g_act [(size_t)NEXP * CAP * HDIM];   // act staging (shared then routed)
__device__ __half g_hx  [(size_t)NTOK * DDIM];
__device__ __half g_w1t [(size_t)NEXP * HDIM * DDIM];
__device__ __half g_w3t [(size_t)NEXP * HDIM * DDIM];
__device__ __half g_w2t [(size_t)NEXP * DDIM * HDIM];
__device__ __half g_sw1t[(size_t)2 * HDIM * DDIM];
__device__ __half g_sw3t[(size_t)2 * HDIM * DDIM];
__device__ __half g_sw2c[(size_t)DDIM * 2 * HDIM];
__device__ int    g_topi[NTOK * 2];
__device__ float  g_wts [NTOK * 2];
__device__ int    g_cnt [NEXP];
__device__ int    g_tokl[NEXP * NTOK];
__device__ float  g_wl  [NEXP * NTOK];
__device__ int    g_ktok[NEXP * CAP];
__device__ float  g_kw  [NEXP * CAP];
__device__ int    g_mk  [NEXP];
__device__ int    g_pos [NTOK * 2];

// ---------------- helpers ----------------
__device__ __forceinline__ void cpasync16(uint32_t dst, const void* src, int srcsz) {
    asm volatile("cp.async.cg.shared.global [%0], [%1], 16, %2;"
                 :: "r"(dst), "l"(src), "r"(srcsz));
}
#define CP_COMMIT() asm volatile("cp.async.commit_group;" ::: "memory")

// ---------------- prep kernels ----------------
__global__ void tohalf_kernel(const float* __restrict__ x, __half* __restrict__ o, int n4) {
    int i = blockIdx.x * blockDim.x + threadIdx.x;
    if (i >= n4) return;
    float4 v = reinterpret_cast<const float4*>(x)[i];
    __half2* o2 = reinterpret_cast<__half2*>(o);
    o2[i * 2 + 0] = __floats2half2_rn(v.x, v.y);
    o2[i * 2 + 1] = __floats2half2_rn(v.z, v.w);
}

// src [z][K][N] fp32 -> dst half element at z*dzs + n*dln + k
__global__ void transpose_h(const float* __restrict__ src, __half* __restrict__ dst,
                            int K, int N, size_t dzs, size_t dln) {
    __shared__ float t[32][33];
    int z = blockIdx.z;
    const float* s = src + (size_t)z * K * N;
    __half* d = dst + (size_t)z * dzs;
    int k0 = blockIdx.y * 32, n0 = blockIdx.x * 32;
    int tx = threadIdx.x, ty = threadIdx.y;
#pragma unroll
    for (int i = ty; i < 32; i += 8)
        t[i][tx] = s[(size_t)(k0 + i) * N + (n0 + tx)];
    __syncthreads();
#pragma unroll
    for (int i = ty; i < 32; i += 8)
        d[(size_t)(n0 + i) * dln + (k0 + tx)] = __float2half_rn(t[tx][i]);
}

// ---------------- gate: exact fp32 ----------------
__global__ void gate_kernel(const float* __restrict__ x, const float* __restrict__ gw,
                            const float* __restrict__ gb,
                            int* __restrict__ topi, float* __restrict__ wts) {
    int t = (blockIdx.x * blockDim.x + threadIdx.x) >> 5;
    int lane = threadIdx.x & 31;
    if (t >= NTOK) return;
    const float* xr = x + (size_t)t * DDIM;
    float s[NEXP];
#pragma unroll
    for (int e = 0; e < NEXP; e++) s[e] = 0.f;
    for (int i = lane; i < DDIM; i += 32) {
        float xv = xr[i];
        const float4* w4 = reinterpret_cast<const float4*>(gw + (size_t)i * NEXP);
#pragma unroll
        for (int q = 0; q < 4; q++) {
            float4 w = w4[q];
            s[q*4+0] += xv * w.x; s[q*4+1] += xv * w.y;
            s[q*4+2] += xv * w.z; s[q*4+3] += xv * w.w;
        }
    }
#pragma unroll
    for (int e = 0; e < NEXP; e++)
#pragma unroll
        for (int off = 16; off > 0; off >>= 1)
            s[e] += __shfl_xor_sync(0xffffffffu, s[e], off);
    if (lane == 0) {
        float mx = s[0];
#pragma unroll
        for (int e = 1; e < NEXP; e++) mx = fmaxf(mx, s[e]);
        float sum = 0.f, sc[NEXP];
#pragma unroll
        for (int e = 0; e < NEXP; e++) { sc[e] = expf(s[e] - mx); sum += sc[e]; }
        float inv = 1.f / sum;
#pragma unroll
        for (int e = 0; e < NEXP; e++) sc[e] = sc[e] * inv + gb[e];
        int i0 = 0; float v0 = sc[0];
#pragma unroll
        for (int e = 1; e < NEXP; e++) if (sc[e] > v0) { v0 = sc[e]; i0 = e; }
        int i1 = 0; float v1 = -1e30f;
#pragma unroll
        for (int e = 0; e < NEXP; e++) if (e != i0 && sc[e] > v1) { v1 = sc[e]; i1 = e; }
        topi[t*2+0] = i0; topi[t*2+1] = i1;
        wts [t*2+0] = s[i0]; wts[t*2+1] = s[i1];
    }
}

__global__ void assign_kernel(const int* __restrict__ topi, const float* __restrict__ wts,
                              int* __restrict__ cnt, int* __restrict__ tokl,
                              float* __restrict__ wl) {
    int i = blockIdx.x * blockDim.x + threadIdx.x;
    if (i >= NTOK * 2) return;
    int e = topi[i];
    int p = atomicAdd(&cnt[e], 1);
    tokl[(size_t)e * NTOK + p] = i >> 1;
    wl  [(size_t)e * NTOK + p] = wts[i];
}

__device__ __forceinline__ unsigned fkey(float f) {
    unsigned u = __float_as_uint(f);
    return (u & 0x80000000u) ? ~u : (u | 0x80000000u);
}

// selection + inverse position map: pos[token*2 + which] = e*CAP + slot
__global__ void select_kernel(const int* __restrict__ cnt, const int* __restrict__ tokl,
                              const float* __restrict__ wl, const int* __restrict__ topi,
                              int* __restrict__ ktok, float* __restrict__ kw,
                              int* __restrict__ mk, int* __restrict__ pos) {
    int e = blockIdx.x;
    int n = cnt[e];
    const int*   tl = tokl + (size_t)e * NTOK;
    const float* wv = wl   + (size_t)e * NTOK;
    int tid = threadIdx.x;

    if (n <= CAP) {
        for (int i = tid; i < n; i += blockDim.x) {
            int tkn = tl[i];
            ktok[(size_t)e * CAP + i] = tkn;
            kw  [(size_t)e * CAP + i] = wv[i];
            int which = (topi[tkn * 2] == e) ? 0 : 1;
            pos[tkn * 2 + which] = e * CAP + i;
        }
        if (tid == 0) mk[e] = n;
        return;
    }
    __shared__ int hist[256];
    __shared__ unsigned s_prefix;
    __shared__ int s_rem, s_nk, s_neq;
    __shared__ int eq_tok[2048];
    __shared__ int eq_src[2048];
    if (tid == 0) { s_prefix = 0u; s_rem = CAP; }
    __syncthreads();
    for (int shift = 24; shift >= 0; shift -= 8) {
        for (int b = tid; b < 256; b += blockDim.x) hist[b] = 0;
        __syncthreads();
        unsigned pfx = s_prefix;
        for (int i = tid; i < n; i += blockDim.x) {
            unsigned key = fkey(wv[i]);
            if (shift == 24 || (key >> (shift + 8)) == pfx)
                atomicAdd(&hist[(key >> shift) & 255], 1);
        }
        __syncthreads();
        if (tid == 0) {
            int rem = s_rem;
            int b = 255;
            for (; b > 0; b--) { if (hist[b] >= rem) break; rem -= hist[b]; }
            s_prefix = (pfx << 8) | (unsigned)b;
            s_rem = rem;
        }
        __syncthreads();
    }
    unsigned T = s_prefix;
    int rem = s_rem;
    if (tid == 0) { s_nk = 0; s_neq = 0; }
    __syncthreads();
    for (int i = tid; i < n; i += blockDim.x) {
        unsigned key = fkey(wv[i]);
        if (key > T) {
            int p = atomicAdd(&s_nk, 1);
            int tkn = tl[i];
            ktok[(size_t)e * CAP + p] = tkn;
            kw  [(size_t)e * CAP + p] = wv[i];
            int which = (topi[tkn * 2] == e) ? 0 : 1;
            pos[tkn * 2 + which] = e * CAP + p;
        } else if (key == T) {
            int p = atomicAdd(&s_neq, 1);
            if (p < 2048) { eq_tok[p] = tl[i]; eq_src[p] = i; }
        }
    }
    __syncthreads();
    int neq = min(s_neq, 2048);
    for (int j = tid; j < neq; j += blockDim.x) {
        int tj = eq_tok[j];
        int rank = 0;
        for (int l = 0; l < neq; l++) rank += (eq_tok[l] < tj);
        if (rank < rem) {
            int p = atomicAdd(&s_nk, 1);
            ktok[(size_t)e * CAP + p] = tj;
            kw  [(size_t)e * CAP + p] = wv[eq_src[j]];
            int which = (topi[tj * 2] == e) ? 0 : 1;
            pos[tj * 2 + which] = e * CAP + p;
        }
    }
    __syncthreads();
    if (tid == 0) mk[e] = s_nk;
}

// ---------------- fp16 mma.sync GEMM: C[M,N] = A[M,K] @ Bt[N,K]^T ----------------
// CTA 128x256, 8 warps (warp tile 64x64), KC=64, double-buffered cp.async.
// MODE 0: C(half) = acc             MODE 1: C(half) = silu(acc) * U(half)
// MODE 2: C(float) = acc * scale    MODE 3: C(half) = acc * roww[r] * scale
template<int MODE, bool GATHER>
__global__ void __launch_bounds__(256, 1)
gemm_h(const __half* __restrict__ A, size_t sAz, int lda,
       const __half* __restrict__ Bt, size_t sBz,
       void* __restrict__ Cv, size_t sCz, int ldc,
       const __half* __restrict__ U, size_t sUz,
       const int* __restrict__ mlist, int Mmax, int N, int K,
       const int* __restrict__ gidx, const float* __restrict__ roww,
       float outscale)
{
    extern __shared__ char smem[];
    int z = blockIdx.z;
    int M = mlist ? mlist[z] : Mmax;
    int row0 = blockIdx.y * BM;
    if (row0 >= M) return;
    int col0 = blockIdx.x * BN;

    A  += sAz * z;
    Bt += sBz * z;
    if (MODE == 1) U += sUz * z;
    const int*   gl = gidx ? gidx + (size_t)z * CAP : nullptr;
    const float* rw = roww ? roww + (size_t)z * CAP : nullptr;
    __half* Ch = (__half*)Cv + sCz * z;
    float*  Cf = (float*)Cv;

    int tid = threadIdx.x;
    int lane = tid & 31, wid = tid >> 5;
    int wm = wid >> 2, wn = wid & 3;          // warp tile (64 rows x 64 cols)
    int g = lane >> 2, t4 = lane & 3;

    // staging assignments: A row = tid>>1 (2 threads/row, 64B each); B row = tid
    int arow = tid >> 1, aseg = tid & 1;
    const __half* aptr = A;
    int asz = 0;
    {
        int r = row0 + arow;
        if (r < M) {
            int gr = GATHER ? gl[r] : r;
            aptr = A + (size_t)gr * lda + aseg * 32;
            asz = 16;
        }
    }
    const __half* bptr = Bt + (size_t)(col0 + tid) * K;
    uint32_t sbase = (uint32_t)__cvta_generic_to_shared(smem);
    uint32_t aoff = (uint32_t)(arow * PADK + aseg * 32) * 2;
    uint32_t boff = (uint32_t)A_BYTES + (uint32_t)tid * (PADK * 2);

    float acc[4][8][4];
#pragma unroll
    for (int mt = 0; mt < 4; mt++)
#pragma unroll
        for (int nt = 0; nt < 8; nt++)
#pragma unroll
            for (int q = 0; q < 4; q++) acc[mt][nt][q] = 0.f;

    int nk = K / KC;
    // prologue: kb=0 -> buf0
    {
        uint32_t dA = sbase + aoff;
        uint32_t dB = sbase + boff;
#pragma unroll
        for (int c = 0; c < 4; c++) cpasync16(dA + c * 16, aptr + c * 8, asz);
#pragma unroll
        for (int c = 0; c < 8; c++) cpasync16(dB + c * 16, bptr + c * 8, 16);
        CP_COMMIT();
    }

    for (int kb = 0; kb < nk; kb++) {
        if (kb + 1 < nk) {
            uint32_t bs = ((kb + 1) & 1) * BUF_BYTES;
            const __half* as = aptr + (kb + 1) * KC;
            const __half* bsrc = bptr + (kb + 1) * KC;
            uint32_t dA = sbase + bs + aoff;
            uint32_t dB = sbase + bs + boff;
#pragma unroll
            for (int c = 0; c < 4; c++) cpasync16(dA + c * 16, as + c * 8, asz);
#pragma unroll
            for (int c = 0; c < 8; c++) cpasync16(dB + c * 16, bsrc + c * 8, 16);
            CP_COMMIT();
            asm volatile("cp.async.wait_group 1;" ::: "memory");
        } else {
            asm volatile("cp.async.wait_group 0;" ::: "memory");
        }
        __syncthreads();

        const uint32_t* As32 = (const uint32_t*)(smem + (kb & 1) * BUF_BYTES);
        const uint32_t* Bs32 = (const uint32_t*)(smem + (kb & 1) * BUF_BYTES + A_BYTES);
#pragma unroll
        for (int ks = 0; ks < 4; ks++) {
            uint32_t af[4][4], bf[8][2];
#pragma unroll
            for (int mt = 0; mt < 4; mt++) {
                int rb = wm * 64 + mt * 16 + g;
                const uint32_t* p0 = As32 + rb * 36 + ks * 8 + t4;
                const uint32_t* p1 = p0 + 8 * 36;
                af[mt][0] = p0[0]; af[mt][1] = p1[0];
                af[mt][2] = p0[4]; af[mt][3] = p1[4];
            }
#pragma unroll
            for (int nt = 0; nt < 8; nt++) {
                int rbn = wn * 64 + nt * 8 + g;
                const uint32_t* q = Bs32 + rbn * 36 + ks * 8 + t4;
                bf[nt][0] = q[0]; bf[nt][1] = q[4];
            }
#pragma unroll
            for (int mt = 0; mt < 4; mt++)
#pragma unroll
                for (int nt = 0; nt < 8; nt++)
                    asm volatile(
                        "mma.sync.aligned.m16n8k16.row.col.f32.f16.f16.f32 "
                        "{%0,%1,%2,%3}, {%4,%5,%6,%7}, {%8,%9}, {%0,%1,%2,%3};"
                        : "+f"(acc[mt][nt][0]), "+f"(acc[mt][nt][1]),
                          "+f"(acc[mt][nt][2]), "+f"(acc[mt][nt][3])
                        : "r"(af[mt][0]), "r"(af[mt][1]), "r"(af[mt][2]), "r"(af[mt][3]),
                          "r"(bf[nt][0]), "r"(bf[nt][1]));
        }
        __syncthreads();
    }

    // ---------------- epilogue ----------------
#pragma unroll
    for (int mt = 0; mt < 4; mt++) {
#pragma unroll
        for (int h = 0; h < 2; h++) {
            int rr = row0 + wm * 64 + mt * 16 + g + h * 8;
            if (rr >= M) continue;
            float scl = outscale;
            if (MODE == 3) scl = rw[rr] * outscale;
#pragma unroll
            for (int nt = 0; nt < 8; nt++) {
                int cc = col0 + wn * 64 + nt * 8 + t4 * 2;
                float v0 = acc[mt][nt][h * 2 + 0];
                float v1 = acc[mt][nt][h * 2 + 1];
                size_t off = (size_t)rr * ldc + cc;
                if (MODE == 0) {
                    *reinterpret_cast<__half2*>(Ch + off) = __floats2half2_rn(v0, v1);
                } else if (MODE == 1) {
                    __half2 u2 = *reinterpret_cast<const __half2*>(U + off);
                    float s0 = v0 / (1.f + __expf(-v0));
                    float s1 = v1 / (1.f + __expf(-v1));
                    *reinterpret_cast<__half2*>(Ch + off) =
                        __floats2half2_rn(s0 * __low2float(u2), s1 * __high2float(u2));
                } else if (MODE == 2) {
                    float2 v = make_float2(v0 * outscale, v1 * outscale);
                    *reinterpret_cast<float2*>(Cf + off) = v;
                } else { // MODE 3
                    *reinterpret_cast<__half2*>(Ch + off) = __floats2half2_rn(v0 * scl, v1 * scl);
                }
            }
        }
    }
}

// ---------------- final combine: out[t] += y[pos0] + y[pos1] ----------------
__global__ void combine_kernel(const int* __restrict__ pos, const __half* __restrict__ y,
                               float* __restrict__ out) {
    int i = blockIdx.x * blockDim.x + threadIdx.x;
    int tok = i >> 8;               // 256 groups of 4 cols per token
    int c = (i & 255) * 4;
    int p0 = pos[tok * 2], p1 = pos[tok * 2 + 1];
    float4 o = *reinterpret_cast<float4*>(out + (size_t)tok * DDIM + c);
    if (p0 >= 0) {
        __half2 a = *reinterpret_cast<const __half2*>(y + (size_t)p0 * DDIM + c);
        __half2 b = *reinterpret_cast<const __half2*>(y + (size_t)p0 * DDIM + c + 2);
        o.x += __low2float(a); o.y += __high2float(a);
        o.z += __low2float(b); o.w += __high2float(b);
    }
    if (p1 >= 0) {
        __half2 a = *reinterpret_cast<const __half2*>(y + (size_t)p1 * DDIM + c);
        __half2 b = *reinterpret_cast<const __half2*>(y + (size_t)p1 * DDIM + c + 2);
        o.x += __low2float(a); o.y += __high2float(a);
        o.z += __low2float(b); o.w += __high2float(b);
    }
    *reinterpret_cast<float4*>(out + (size_t)tok * DDIM + c) = o;
}

// ---------------- host launcher ----------------
extern "C" void kernel_launch(void* const* d_in, const int* in_sizes, int n_in,
                              void* d_out, int out_size) {
    const float* x   = (const float*)d_in[0];
    const float* gw  = (const float*)d_in[1];
    const float* gb  = (const float*)d_in[2];
    const float* ew1 = (const float*)d_in[3];
    const float* ew3 = (const float*)d_in[4];
    const float* ew2 = (const float*)d_in[5];
    const float* sw1 = (const float*)d_in[6];
    const float* sw3 = (const float*)d_in[7];
    const float* sw2 = (const float*)d_in[8];
    float* out = (float*)d_out;

    __half *ubuf, *act, *hx, *w1t, *w3t, *w2t, *sw1t, *sw3t, *sw2c;
    float *wts, *wl, *kw;
    int *topi, *cnt, *tokl, *ktok, *mk, *pos;
    cudaGetSymbolAddress((void**)&ubuf, g_ubuf);
    cudaGetSymbolAddress((void**)&act,  g_act);
    cudaGetSymbolAddress((void**)&hx,   g_hx);
    cudaGetSymbolAddress((void**)&w1t,  g_w1t);
    cudaGetSymbolAddress((void**)&w3t,  g_w3t);
    cudaGetSymbolAddress((void**)&w2t,  g_w2t);
    cudaGetSymbolAddress((void**)&sw1t, g_sw1t);
    cudaGetSymbolAddress((void**)&sw3t, g_sw3t);
    cudaGetSymbolAddress((void**)&sw2c, g_sw2c);
    cudaGetSymbolAddress((void**)&topi, g_topi);
    cudaGetSymbolAddress((void**)&wts,  g_wts);
    cudaGetSymbolAddress((void**)&cnt,  g_cnt);
    cudaGetSymbolAddress((void**)&tokl, g_tokl);
    cudaGetSymbolAddress((void**)&wl,   g_wl);
    cudaGetSymbolAddress((void**)&ktok, g_ktok);
    cudaGetSymbolAddress((void**)&kw,   g_kw);
    cudaGetSymbolAddress((void**)&mk,   g_mk);
    cudaGetSymbolAddress((void**)&pos,  g_pos);

    cudaFuncSetAttribute((const void*)gemm_h<0,false>, cudaFuncAttributeMaxDynamicSharedMemorySize, SMEM_BYTES);
    cudaFuncSetAttribute((const void*)gemm_h<1,false>, cudaFuncAttributeMaxDynamicSharedMemorySize, SMEM_BYTES);
    cudaFuncSetAttribute((const void*)gemm_h<2,false>, cudaFuncAttributeMaxDynamicSharedMemorySize, SMEM_BYTES);
    cudaFuncSetAttribute((const void*)gemm_h<0,true>,  cudaFuncAttributeMaxDynamicSharedMemorySize, SMEM_BYTES);
    cudaFuncSetAttribute((const void*)gemm_h<1,true>,  cudaFuncAttributeMaxDynamicSharedMemorySize, SMEM_BYTES);
    cudaFuncSetAttribute((const void*)gemm_h<3,false>, cudaFuncAttributeMaxDynamicSharedMemorySize, SMEM_BYTES);

    cudaMemsetAsync(cnt, 0, NEXP * sizeof(int), 0);
    cudaMemsetAsync(pos, 0xFF, NTOK * 2 * sizeof(int), 0);

    // prep: fp16 conversions + transposed weights
    tohalf_kernel<<<(NTOK * DDIM / 4 + 255) / 256, 256>>>(x, hx, NTOK * DDIM / 4);
    dim3 tb(32, 8);
    transpose_h<<<dim3(HDIM/32, DDIM/32, NEXP), tb>>>(ew1, w1t, DDIM, HDIM, (size_t)HDIM*DDIM, DDIM);
    transpose_h<<<dim3(HDIM/32, DDIM/32, NEXP), tb>>>(ew3, w3t, DDIM, HDIM, (size_t)HDIM*DDIM, DDIM);
    transpose_h<<<dim3(DDIM/32, HDIM/32, NEXP), tb>>>(ew2, w2t, HDIM, DDIM, (size_t)DDIM*HDIM, HDIM);
    transpose_h<<<dim3(HDIM/32, DDIM/32, 2), tb>>>(sw1, sw1t, DDIM, HDIM, (size_t)HDIM*DDIM, DDIM);
    transpose_h<<<dim3(HDIM/32, DDIM/32, 2), tb>>>(sw3, sw3t, DDIM, HDIM, (size_t)HDIM*DDIM, DDIM);
    transpose_h<<<dim3(DDIM/32, HDIM/32, 2), tb>>>(sw2, sw2c, HDIM, DDIM, (size_t)HDIM, (size_t)2*HDIM);

    // routing (exact fp32)
    gate_kernel<<<NTOK / 8, 256>>>(x, gw, gb, topi, wts);
    assign_kernel<<<(NTOK * 2 + 255) / 256, 256>>>(topi, wts, cnt, tokl, wl);
    select_kernel<<<NEXP, 256>>>(cnt, tokl, wl, topi, ktok, kw, mk, pos);

    // ---- shared experts: u/act staged K-concat [NTOK][2*HDIM] ----
    gemm_h<0,false><<<dim3(HDIM/BN, NTOK/BM, 2), 256, SMEM_BYTES>>>(
        hx, 0, DDIM, sw3t, (size_t)HDIM*DDIM, ubuf, (size_t)HDIM, 2*HDIM,
        nullptr, 0, nullptr, NTOK, HDIM, DDIM, nullptr, nullptr, 1.f);
    gemm_h<1,false><<<dim3(HDIM/BN, NTOK/BM, 2), 256, SMEM_BYTES>>>(
        hx, 0, DDIM, sw1t, (size_t)HDIM*DDIM, act, (size_t)HDIM, 2*HDIM,
        ubuf, (size_t)HDIM, nullptr, NTOK, HDIM, DDIM, nullptr, nullptr, 1.f);
    // both shared down-projs as ONE K=4096 GEMM, direct fp32 store (writes ALL of out)
    gemm_h<2,false><<<dim3(DDIM/BN, NTOK/BM, 1), 256, SMEM_BYTES>>>(
        act, 0, 2*HDIM, sw2c, 0, out, 0, DDIM,
        nullptr, 0, nullptr, NTOK, DDIM, 2*HDIM, nullptr, nullptr, 0.5f);

    // ---- routed experts ----
    gemm_h<0,true><<<dim3(HDIM/BN, (CAP+BM-1)/BM, NEXP), 256, SMEM_BYTES>>>(
        hx, 0, DDIM, w3t, (size_t)HDIM*DDIM, ubuf, (size_t)CAP*HDIM, HDIM,
        nullptr, 0, mk, CAP, HDIM, DDIM, ktok, nullptr, 1.f);
    gemm_h<1,true><<<dim3(HDIM/BN, (CAP+BM-1)/BM, NEXP), 256, SMEM_BYTES>>>(
        hx, 0, DDIM, w1t, (size_t)HDIM*DDIM, act, (size_t)CAP*HDIM, HDIM,
        ubuf, (size_t)CAP*HDIM, mk, CAP, HDIM, DDIM, ktok, nullptr, 1.f);
    // routed down-proj: weighted direct store into y staging (reuses g_ubuf)
    gemm_h<3,false><<<dim3(DDIM/BN, (CAP+BM-1)/BM, NEXP), 256, SMEM_BYTES>>>(
        act, (size_t)CAP*HDIM, HDIM, w2t, (size_t)DDIM*HDIM, ubuf, (size_t)CAP*DDIM, DDIM,
        nullptr, 0, mk, CAP, DDIM, HDIM, nullptr, kw, 1.f);

    // final gather-sum (no atomics)
    combine_kernel<<<NTOK * 256 / 256, 256>>>(pos, ubuf, out);
}

// round 5
// speedup vs baseline: 1.3294x; 1.0298x over previous
#include <cuda_runtime.h>
#include <cuda_fp16.h>
#include <cstdint>

#define NTOK 16384
#define DDIM 1024
#define HDIM 2048
#define NEXP 16
#define CAP  2560
#define BM 128
#define BN 256
#define KC 64
#define A_ROWB 144                   // 64 halves + 8 pad, bytes
#define B_ROWB 528                   // 256 halves + 8 pad, bytes
#define A_BYTES (BM * A_ROWB)        // 18432
#define B_BYTES (KC * B_ROWB)        // 33792
#define BUF_BYTES (A_BYTES + B_BYTES)
#define SMEM_BYTES (2 * BUF_BYTES)   // 104448

// ---------------- scratch (device globals; no allocation) ----------------
__device__ __half g_ubuf[(size_t)NEXP * CAP * HDIM];   // u staging; later reused for y
__device__ __half g_act [(size_t)NEXP * CAP * HDIM];   // act staging (shared then routed)
__device__ __half g_hx  [(size_t)NTOK * DDIM];
__device__ __half g_w1h [(size_t)NEXP * DDIM * HDIM];
__device__ __half g_w3h [(size_t)NEXP * DDIM * HDIM];
__device__ __half g_w2h [(size_t)NEXP * HDIM * DDIM];
__device__ __half g_sw1h[(size_t)2 * DDIM * HDIM];
__device__ __half g_sw3h[(size_t)2 * DDIM * HDIM];
__device__ __half g_sw2h[(size_t)2 * HDIM * DDIM];
__device__ int    g_topi[NTOK * 2];
__device__ float  g_wts [NTOK * 2];
__device__ int    g_cnt [NEXP];
__device__ int    g_tokl[NEXP * NTOK];
__device__ float  g_wl  [NEXP * NTOK];
__device__ int    g_ktok[NEXP * CAP];
__device__ float  g_kw  [NEXP * CAP];
__device__ int    g_mk  [NEXP];
__device__ int    g_pos [NTOK * 2];

// ---------------- helpers ----------------
__device__ __forceinline__ void cpasync16(uint32_t dst, const void* src, int srcsz) {
    asm volatile("cp.async.cg.shared.global [%0], [%1], 16, %2;"
                 :: "r"(dst), "l"(src), "r"(srcsz));
}
#define CP_COMMIT() asm volatile("cp.async.commit_group;" ::: "memory")

// ---------------- prep: fp32 -> fp16 elementwise ----------------
__global__ void tohalf_kernel(const float* __restrict__ x, __half* __restrict__ o, int n4) {
    int i = blockIdx.x * blockDim.x + threadIdx.x;
    if (i >= n4) return;
    float4 v = reinterpret_cast<const float4*>(x)[i];
    __half2* o2 = reinterpret_cast<__half2*>(o);
    o2[i * 2 + 0] = __floats2half2_rn(v.x, v.y);
    o2[i * 2 + 1] = __floats2half2_rn(v.z, v.w);
}

// ---------------- gate: exact fp32 ----------------
__global__ void gate_kernel(const float* __restrict__ x, const float* __restrict__ gw,
                            const float* __restrict__ gb,
                            int* __restrict__ topi, float* __restrict__ wts) {
    int t = (blockIdx.x * blockDim.x + threadIdx.x) >> 5;
    int lane = threadIdx.x & 31;
    if (t >= NTOK) return;
    const float* xr = x + (size_t)t * DDIM;
    float s[NEXP];
#pragma unroll
    for (int e = 0; e < NEXP; e++) s[e] = 0.f;
    for (int i = lane; i < DDIM; i += 32) {
        float xv = xr[i];
        const float4* w4 = reinterpret_cast<const float4*>(gw + (size_t)i * NEXP);
#pragma unroll
        for (int q = 0; q < 4; q++) {
            float4 w = w4[q];
            s[q*4+0] += xv * w.x; s[q*4+1] += xv * w.y;
            s[q*4+2] += xv * w.z; s[q*4+3] += xv * w.w;
        }
    }
#pragma unroll
    for (int e = 0; e < NEXP; e++)
#pragma unroll
        for (int off = 16; off > 0; off >>= 1)
            s[e] += __shfl_xor_sync(0xffffffffu, s[e], off);
    if (lane == 0) {
        float mx = s[0];
#pragma unroll
        for (int e = 1; e < NEXP; e++) mx = fmaxf(mx, s[e]);
        float sum = 0.f, sc[NEXP];
#pragma unroll
        for (int e = 0; e < NEXP; e++) { sc[e] = expf(s[e] - mx); sum += sc[e]; }
        float inv = 1.f / sum;
#pragma unroll
        for (int e = 0; e < NEXP; e++) sc[e] = sc[e] * inv + gb[e];
        int i0 = 0; float v0 = sc[0];
#pragma unroll
        for (int e = 1; e < NEXP; e++) if (sc[e] > v0) { v0 = sc[e]; i0 = e; }
        int i1 = 0; float v1 = -1e30f;
#pragma unroll
        for (int e = 0; e < NEXP; e++) if (e != i0 && sc[e] > v1) { v1 = sc[e]; i1 = e; }
        topi[t*2+0] = i0; topi[t*2+1] = i1;
        wts [t*2+0] = s[i0]; wts[t*2+1] = s[i1];
    }
}

__global__ void assign_kernel(const int* __restrict__ topi, const float* __restrict__ wts,
                              int* __restrict__ cnt, int* __restrict__ tokl,
                              float* __restrict__ wl) {
    int i = blockIdx.x * blockDim.x + threadIdx.x;
    if (i >= NTOK * 2) return;
    int e = topi[i];
    int p = atomicAdd(&cnt[e], 1);
    tokl[(size_t)e * NTOK + p] = i >> 1;
    wl  [(size_t)e * NTOK + p] = wts[i];
}

__device__ __forceinline__ unsigned fkey(float f) {
    unsigned u = __float_as_uint(f);
    return (u & 0x80000000u) ? ~u : (u | 0x80000000u);
}

// selection + inverse position map: pos[token*2 + which] = e*CAP + slot
__global__ void select_kernel(const int* __restrict__ cnt, const int* __restrict__ tokl,
                              const float* __restrict__ wl, const int* __restrict__ topi,
                              int* __restrict__ ktok, float* __restrict__ kw,
                              int* __restrict__ mk, int* __restrict__ pos) {
    int e = blockIdx.x;
    int n = cnt[e];
    const int*   tl = tokl + (size_t)e * NTOK;
    const float* wv = wl   + (size_t)e * NTOK;
    int tid = threadIdx.x;

    if (n <= CAP) {
        for (int i = tid; i < n; i += blockDim.x) {
            int tkn = tl[i];
            ktok[(size_t)e * CAP + i] = tkn;
            kw  [(size_t)e * CAP + i] = wv[i];
            int which = (topi[tkn * 2] == e) ? 0 : 1;
            pos[tkn * 2 + which] = e * CAP + i;
        }
        if (tid == 0) mk[e] = n;
        return;
    }
    __shared__ int hist[256];
    __shared__ unsigned s_prefix;
    __shared__ int s_rem, s_nk, s_neq;
    __shared__ int eq_tok[2048];
    __shared__ int eq_src[2048];
    if (tid == 0) { s_prefix = 0u; s_rem = CAP; }
    __syncthreads();
    for (int shift = 24; shift >= 0; shift -= 8) {
        for (int b = tid; b < 256; b += blockDim.x) hist[b] = 0;
        __syncthreads();
        unsigned pfx = s_prefix;
        for (int i = tid; i < n; i += blockDim.x) {
            unsigned key = fkey(wv[i]);
            if (shift == 24 || (key >> (shift + 8)) == pfx)
                atomicAdd(&hist[(key >> shift) & 255], 1);
        }
        __syncthreads();
        if (tid == 0) {
            int rem = s_rem;
            int b = 255;
            for (; b > 0; b--) { if (hist[b] >= rem) break; rem -= hist[b]; }
            s_prefix = (pfx << 8) | (unsigned)b;
            s_rem = rem;
        }
        __syncthreads();
    }
    unsigned T = s_prefix;
    int rem = s_rem;
    if (tid == 0) { s_nk = 0; s_neq = 0; }
    __syncthreads();
    for (int i = tid; i < n; i += blockDim.x) {
        unsigned key = fkey(wv[i]);
        if (key > T) {
            int p = atomicAdd(&s_nk, 1);
            int tkn = tl[i];
            ktok[(size_t)e * CAP + p] = tkn;
            kw  [(size_t)e * CAP + p] = wv[i];
            int which = (topi[tkn * 2] == e) ? 0 : 1;
            pos[tkn * 2 + which] = e * CAP + p;
        } else if (key == T) {
            int p = atomicAdd(&s_neq, 1);
            if (p < 2048) { eq_tok[p] = tl[i]; eq_src[p] = i; }
        }
    }
    __syncthreads();
    int neq = min(s_neq, 2048);
    for (int j = tid; j < neq; j += blockDim.x) {
        int tj = eq_tok[j];
        int rank = 0;
        for (int l = 0; l < neq; l++) rank += (eq_tok[l] < tj);
        if (rank < rem) {
            int p = atomicAdd(&s_nk, 1);
            ktok[(size_t)e * CAP + p] = tj;
            kw  [(size_t)e * CAP + p] = wv[eq_src[j]];
            int which = (topi[tj * 2] == e) ? 0 : 1;
            pos[tj * 2 + which] = e * CAP + p;
        }
    }
    __syncthreads();
    if (tid == 0) mk[e] = s_nk;
}

// ---------------- fp16 mma.sync GEMM: C[M,N] = A[M,K] @ B[K,N] ----------------
// A row-major [M][K] (opt. row-gathered), B row-major K-major [K][N].
// CTA 128x256, 8 warps (warp tile 64x64), KC=64, double-buffered cp.async,
// ldmatrix.x4 (A) + ldmatrix.x4.trans (B) fragment loads.
// MODE 0: C(half)=acc   MODE 1: C(half)=silu(acc)*U   MODE 2: C(float)=acc*scale
// MODE 3: C(half)=acc*roww[r]*scale
template<int MODE, bool GATHER>
__global__ void __launch_bounds__(256, 1)
gemm_h(const __half* __restrict__ A, size_t sAz, int lda,
       const __half* __restrict__ B, size_t sBz,
       void* __restrict__ Cv, size_t sCz, int ldc,
       const __half* __restrict__ U, size_t sUz,
       const int* __restrict__ mlist, int Mmax, int N, int K,
       const int* __restrict__ gidx, const float* __restrict__ roww,
       float outscale)
{
    extern __shared__ char smem[];
    int z = blockIdx.z;
    int M = mlist ? mlist[z] : Mmax;
    int row0 = blockIdx.y * BM;
    if (row0 >= M) return;
    int col0 = blockIdx.x * BN;

    A += sAz * z;
    B += sBz * z;
    if (MODE == 1) U += sUz * z;
    const int*   gl = gidx ? gidx + (size_t)z * CAP : nullptr;
    const float* rw = roww ? roww + (size_t)z * CAP : nullptr;
    __half* Ch = (__half*)Cv + sCz * z;
    float*  Cf = (float*)Cv;

    int tid = threadIdx.x;
    int lane = tid & 31, wid = tid >> 5;
    int wm = wid >> 2, wn = wid & 3;          // warp tile 64x64
    int g = lane >> 2, t4 = lane & 3;

    // --- staging: A row = tid>>1 (2 threads/row, 64B each); B row = tid>>2 (4/row, 128B) ---
    int arow = tid >> 1, aseg = tid & 1;
    const __half* aptr = A;
    int asz = 0;
    {
        int r = row0 + arow;
        if (r < M) {
            int gr = GATHER ? gl[r] : r;
            aptr = A + (size_t)gr * lda + aseg * 32;
            asz = 16;
        }
    }
    int bkrow = tid >> 2, bseg = tid & 3;
    const __half* bptr = B + (size_t)bkrow * N + col0 + bseg * 64;
    uint32_t sbase = (uint32_t)__cvta_generic_to_shared(smem);
    uint32_t aoff = (uint32_t)arow * A_ROWB + (uint32_t)aseg * 64;
    uint32_t boff = (uint32_t)A_BYTES + (uint32_t)bkrow * B_ROWB + (uint32_t)bseg * 128;

    // --- ldmatrix lane addresses (buffer-relative) ---
    // A x4: rows (lane&15), k-half (lane>>4)
    uint32_t a_lm = (uint32_t)(wm * 64 + (lane & 15)) * A_ROWB + (uint32_t)(lane >> 4) * 16;
    // B x4.trans: k-row = ((lane>>3)&1)*8 + (lane&7), n-col base += (lane>>4)*8 halves
    uint32_t b_lm = (uint32_t)A_BYTES
                  + (uint32_t)((((lane >> 3) & 1) * 8 + (lane & 7))) * B_ROWB
                  + (uint32_t)(wn * 64 + (lane >> 4) * 8) * 2;

    float acc[4][8][4];
#pragma unroll
    for (int mt = 0; mt < 4; mt++)
#pragma unroll
        for (int nt = 0; nt < 8; nt++)
#pragma unroll
            for (int q = 0; q < 4; q++) acc[mt][nt][q] = 0.f;

    int nk = K / KC;
    {   // prologue -> buf0
        uint32_t dA = sbase + aoff;
        uint32_t dB = sbase + boff;
#pragma unroll
        for (int c = 0; c < 4; c++) cpasync16(dA + c * 16, aptr + c * 8, asz);
#pragma unroll
        for (int c = 0; c < 8; c++) cpasync16(dB + c * 16, bptr + c * 8, 16);
        CP_COMMIT();
    }

    for (int kb = 0; kb < nk; kb++) {
        if (kb + 1 < nk) {
            uint32_t bs = ((kb + 1) & 1) * BUF_BYTES;
            const __half* as = aptr + (kb + 1) * KC;
            const __half* bsrc = bptr + (size_t)(kb + 1) * KC * N;
            uint32_t dA = sbase + bs + aoff;
            uint32_t dB = sbase + bs + boff;
#pragma unroll
            for (int c = 0; c < 4; c++) cpasync16(dA + c * 16, as + c * 8, asz);
#pragma unroll
            for (int c = 0; c < 8; c++) cpasync16(dB + c * 16, bsrc + c * 8, 16);
            CP_COMMIT();
            asm volatile("cp.async.wait_group 1;" ::: "memory");
        } else {
            asm volatile("cp.async.wait_group 0;" ::: "memory");
        }
        __syncthreads();

        uint32_t bufb = sbase + (kb & 1) * BUF_BYTES;
#pragma unroll
        for (int ks = 0; ks < 4; ks++) {
            uint32_t af[4][4], bf[8][2];
#pragma unroll
            for (int mt = 0; mt < 4; mt++) {
                uint32_t ad = bufb + a_lm + (uint32_t)mt * (16 * A_ROWB) + (uint32_t)ks * 32;
                asm volatile("ldmatrix.sync.aligned.m8n8.x4.shared.b16 {%0,%1,%2,%3}, [%4];"
                             : "=r"(af[mt][0]), "=r"(af[mt][1]), "=r"(af[mt][2]), "=r"(af[mt][3])
                             : "r"(ad));
            }
#pragma unroll
            for (int p = 0; p < 4; p++) {
                uint32_t bd = bufb + b_lm + (uint32_t)ks * (16 * B_ROWB) + (uint32_t)p * 32;
                asm volatile("ldmatrix.sync.aligned.m8n8.x4.trans.shared.b16 {%0,%1,%2,%3}, [%4];"
                             : "=r"(bf[2*p][0]), "=r"(bf[2*p][1]),
                               "=r"(bf[2*p+1][0]), "=r"(bf[2*p+1][1])
                             : "r"(bd));
            }
#pragma unroll
            for (int mt = 0; mt < 4; mt++)
#pragma unroll
                for (int nt = 0; nt < 8; nt++)
                    asm volatile(
                        "mma.sync.aligned.m16n8k16.row.col.f32.f16.f16.f32 "
                        "{%0,%1,%2,%3}, {%4,%5,%6,%7}, {%8,%9}, {%0,%1,%2,%3};"
                        : "+f"(acc[mt][nt][0]), "+f"(acc[mt][nt][1]),
                          "+f"(acc[mt][nt][2]), "+f"(acc[mt][nt][3])
                        : "r"(af[mt][0]), "r"(af[mt][1]), "r"(af[mt][2]), "r"(af[mt][3]),
                          "r"(bf[nt][0]), "r"(bf[nt][1]));
        }
        __syncthreads();
    }

    // ---------------- epilogue ----------------
#pragma unroll
    for (int mt = 0; mt < 4; mt++) {
#pragma unroll
        for (int h = 0; h < 2; h++) {
            int rr = row0 + wm * 64 + mt * 16 + g + h * 8;
            if (rr >= M) continue;
            float scl = outscale;
            if (MODE == 3) scl = rw[rr] * outscale;
#pragma unroll
            for (int nt = 0; nt < 8; nt++) {
                int cc = col0 + wn * 64 + nt * 8 + t4 * 2;
                float v0 = acc[mt][nt][h * 2 + 0];
                float v1 = acc[mt][nt][h * 2 + 1];
                size_t off = (size_t)rr * ldc + cc;
                if (MODE == 0) {
                    *reinterpret_cast<__half2*>(Ch + off) = __floats2half2_rn(v0, v1);
                } else if (MODE == 1) {
                    __half2 u2 = *reinterpret_cast<const __half2*>(U + off);
                    float s0 = v0 / (1.f + __expf(-v0));
                    float s1 = v1 / (1.f + __expf(-v1));
                    *reinterpret_cast<__half2*>(Ch + off) =
                        __floats2half2_rn(s0 * __low2float(u2), s1 * __high2float(u2));
                } else if (MODE == 2) {
                    float2 v = make_float2(v0 * outscale, v1 * outscale);
                    *reinterpret_cast<float2*>(Cf + off) = v;
                } else { // MODE 3
                    *reinterpret_cast<__half2*>(Ch + off) = __floats2half2_rn(v0 * scl, v1 * scl);
                }
            }
        }
    }
}

// ---------------- final combine: out[t] += y[pos0] + y[pos1] ----------------
__global__ void combine_kernel(const int* __restrict__ pos, const __half* __restrict__ y,
                               float* __restrict__ out) {
    int i = blockIdx.x * blockDim.x + threadIdx.x;
    int tok = i >> 8;
    int c = (i & 255) * 4;
    int p0 = pos[tok * 2], p1 = pos[tok * 2 + 1];
    float4 o = *reinterpret_cast<float4*>(out + (size_t)tok * DDIM + c);
    if (p0 >= 0) {
        __half2 a = *reinterpret_cast<const __half2*>(y + (size_t)p0 * DDIM + c);
        __half2 b = *reinterpret_cast<const __half2*>(y + (size_t)p0 * DDIM + c + 2);
        o.x += __low2float(a); o.y += __high2float(a);
        o.z += __low2float(b); o.w += __high2float(b);
    }
    if (p1 >= 0) {
        __half2 a = *reinterpret_cast<const __half2*>(y + (size_t)p1 * DDIM + c);
        __half2 b = *reinterpret_cast<const __half2*>(y + (size_t)p1 * DDIM + c + 2);
        o.x += __low2float(a); o.y += __high2float(a);
        o.z += __low2float(b); o.w += __high2float(b);
    }
    *reinterpret_cast<float4*>(out + (size_t)tok * DDIM + c) = o;
}

// ---------------- host launcher ----------------
extern "C" void kernel_launch(void* const* d_in, const int* in_sizes, int n_in,
                              void* d_out, int out_size) {
    const float* x   = (const float*)d_in[0];
    const float* gw  = (const float*)d_in[1];
    const float* gb  = (const float*)d_in[2];
    const float* ew1 = (const float*)d_in[3];
    const float* ew3 = (const float*)d_in[4];
    const float* ew2 = (const float*)d_in[5];
    const float* sw1 = (const float*)d_in[6];
    const float* sw3 = (const float*)d_in[7];
    const float* sw2 = (const float*)d_in[8];
    float* out = (float*)d_out;

    __half *ubuf, *act, *hx, *w1h, *w3h, *w2h, *sw1h, *sw3h, *sw2h;
    float *wts, *wl, *kw;
    int *topi, *cnt, *tokl, *ktok, *mk, *pos;
    cudaGetSymbolAddress((void**)&ubuf, g_ubuf);
    cudaGetSymbolAddress((void**)&act,  g_act);
    cudaGetSymbolAddress((void**)&hx,   g_hx);
    cudaGetSymbolAddress((void**)&w1h,  g_w1h);
    cudaGetSymbolAddress((void**)&w3h,  g_w3h);
    cudaGetSymbolAddress((void**)&w2h,  g_w2h);
    cudaGetSymbolAddress((void**)&sw1h, g_sw1h);
    cudaGetSymbolAddress((void**)&sw3h, g_sw3h);
    cudaGetSymbolAddress((void**)&sw2h, g_sw2h);
    cudaGetSymbolAddress((void**)&topi, g_topi);
    cudaGetSymbolAddress((void**)&wts,  g_wts);
    cudaGetSymbolAddress((void**)&cnt,  g_cnt);
    cudaGetSymbolAddress((void**)&tokl, g_tokl);
    cudaGetSymbolAddress((void**)&wl,   g_wl);
    cudaGetSymbolAddress((void**)&ktok, g_ktok);
    cudaGetSymbolAddress((void**)&kw,   g_kw);
    cudaGetSymbolAddress((void**)&mk,   g_mk);
    cudaGetSymbolAddress((void**)&pos,  g_pos);

    cudaFuncSetAttribute((const void*)gemm_h<0,false>, cudaFuncAttributeMaxDynamicSharedMemorySize, SMEM_BYTES);
    cudaFuncSetAttribute((const void*)gemm_h<1,false>, cudaFuncAttributeMaxDynamicSharedMemorySize, SMEM_BYTES);
    cudaFuncSetAttribute((const void*)gemm_h<2,false>, cudaFuncAttributeMaxDynamicSharedMemorySize, SMEM_BYTES);
    cudaFuncSetAttribute((const void*)gemm_h<0,true>,  cudaFuncAttributeMaxDynamicSharedMemorySize, SMEM_BYTES);
    cudaFuncSetAttribute((const void*)gemm_h<1,true>,  cudaFuncAttributeMaxDynamicSharedMemorySize, SMEM_BYTES);
    cudaFuncSetAttribute((const void*)gemm_h<3,false>, cudaFuncAttributeMaxDynamicSharedMemorySize, SMEM_BYTES);

    cudaMemsetAsync(cnt, 0, NEXP * sizeof(int), 0);
    cudaMemsetAsync(pos, 0xFF, NTOK * 2 * sizeof(int), 0);

    // prep: fp16 conversions (weights keep natural K-major layout — no transposes)
    tohalf_kernel<<<(NTOK*DDIM/4 + 255)/256, 256>>>(x, hx, NTOK*DDIM/4);
    int we4 = NEXP*DDIM*HDIM/4;
    tohalf_kernel<<<(we4 + 255)/256, 256>>>(ew1, w1h, we4);
    tohalf_kernel<<<(we4 + 255)/256, 256>>>(ew3, w3h, we4);
    tohalf_kernel<<<(we4 + 255)/256, 256>>>(ew2, w2h, we4);
    int ws4 = 2*DDIM*HDIM/4;
    tohalf_kernel<<<(ws4 + 255)/256, 256>>>(sw1, sw1h, ws4);
    tohalf_kernel<<<(ws4 + 255)/256, 256>>>(sw3, sw3h, ws4);
    tohalf_kernel<<<(ws4 + 255)/256, 256>>>(sw2, sw2h, ws4);

    // routing (exact fp32)
    gate_kernel<<<NTOK / 8, 256>>>(x, gw, gb, topi, wts);
    assign_kernel<<<(NTOK * 2 + 255) / 256, 256>>>(topi, wts, cnt, tokl, wl);
    select_kernel<<<NEXP, 256>>>(cnt, tokl, wl, topi, ktok, kw, mk, pos);

    // ---- shared experts: u/act staged K-concat [NTOK][2*HDIM] ----
    gemm_h<0,false><<<dim3(HDIM/BN, NTOK/BM, 2), 256, SMEM_BYTES>>>(
        hx, 0, DDIM, sw3h, (size_t)DDIM*HDIM, ubuf, (size_t)HDIM, 2*HDIM,
        nullptr, 0, nullptr, NTOK, HDIM, DDIM, nullptr, nullptr, 1.f);
    gemm_h<1,false><<<dim3(HDIM/BN, NTOK/BM, 2), 256, SMEM_BYTES>>>(
        hx, 0, DDIM, sw1h, (size_t)DDIM*HDIM, act, (size_t)HDIM, 2*HDIM,
        ubuf, (size_t)HDIM, nullptr, NTOK, HDIM, DDIM, nullptr, nullptr, 1.f);
    // both shared down-projs as ONE K=4096 GEMM (B = sw2h contiguous [2H][D]); writes ALL of out
    gemm_h<2,false><<<dim3(DDIM/BN, NTOK/BM, 1), 256, SMEM_BYTES>>>(
        act, 0, 2*HDIM, sw2h, 0, out, 0, DDIM,
        nullptr, 0, nullptr, NTOK, DDIM, 2*HDIM, nullptr, nullptr, 0.5f);

    // ---- routed experts ----
    gemm_h<0,true><<<dim3(HDIM/BN, (CAP+BM-1)/BM, NEXP), 256, SMEM_BYTES>>>(
        hx, 0, DDIM, w3h, (size_t)DDIM*HDIM, ubuf, (size_t)CAP*HDIM, HDIM,
        nullptr, 0, mk, CAP, HDIM, DDIM, ktok, nullptr, 1.f);
    gemm_h<1,true><<<dim3(HDIM/BN, (CAP+BM-1)/BM, NEXP), 256, SMEM_BYTES>>>(
        hx, 0, DDIM, w1h, (size_t)DDIM*HDIM, act, (size_t)CAP*HDIM, HDIM,
        ubuf, (size_t)CAP*HDIM, mk, CAP, HDIM, DDIM, ktok, nullptr, 1.f);
    // routed down-proj: weighted direct store into y staging (reuses g_ubuf)
    gemm_h<3,false><<<dim3(DDIM/BN, (CAP+BM-1)/BM, NEXP), 256, SMEM_BYTES>>>(
        act, (size_t)CAP*HDIM, HDIM, w2h, (size_t)HDIM*DDIM, ubuf, (size_t)CAP*DDIM, DDIM,
        nullptr, 0, mk, CAP, DDIM, HDIM, nullptr, kw, 1.f);

    // final gather-sum (no atomics)
    combine_kernel<<<NTOK * 256 / 256, 256>>>(pos, ubuf, out);
}

// round 6
// speedup vs baseline: 1.5671x; 1.1788x over previous
#include <cuda_runtime.h>
#include <cuda_fp16.h>
#include <cstdint>

#define NTOK 16384
#define DDIM 1024
#define HDIM 2048
#define NEXP 16
#define CAP  2560
#define BM 128
#define BN 128
#define KC 64
#define A_ROWB 144                   // 64 halves + 8 pad, bytes
#define B_ROWB 272                   // 128 halves + 8 pad, bytes
#define A_BYTES (BM * A_ROWB)        // 18432
#define B_BYTES (KC * B_ROWB)        // 17408
#define BUF_BYTES (A_BYTES + B_BYTES)
#define SMEM_BYTES (2 * BUF_BYTES)   // 71680 -> 2 CTAs/SM

// ---------------- scratch (device globals; no allocation) ----------------
__device__ __half g_ubuf[(size_t)NEXP * CAP * HDIM];   // u staging; later reused for y
__device__ __half g_act [(size_t)NEXP * CAP * HDIM];   // act staging (shared then routed)
__device__ __half g_hx  [(size_t)NTOK * DDIM];
__device__ __half g_w1h [(size_t)NEXP * DDIM * HDIM];
__device__ __half g_w3h [(size_t)NEXP * DDIM * HDIM];
__device__ __half g_w2h [(size_t)NEXP * HDIM * DDIM];
__device__ __half g_sw1h[(size_t)2 * DDIM * HDIM];
__device__ __half g_sw3h[(size_t)2 * DDIM * HDIM];
__device__ __half g_sw2h[(size_t)2 * HDIM * DDIM];
__device__ int    g_topi[NTOK * 2];
__device__ float  g_wts [NTOK * 2];
__device__ int    g_cnt [NEXP];
__device__ int    g_tokl[NEXP * NTOK];
__device__ float  g_wl  [NEXP * NTOK];
__device__ int    g_ktok[NEXP * CAP];
__device__ float  g_kw  [NEXP * CAP];
__device__ int    g_mk  [NEXP];
__device__ int    g_pos [NTOK * 2];

// ---------------- helpers ----------------
__device__ __forceinline__ void cpasync16(uint32_t dst, const void* src, int srcsz) {
    asm volatile("cp.async.cg.shared.global [%0], [%1], 16, %2;"
                 :: "r"(dst), "l"(src), "r"(srcsz));
}
#define CP_COMMIT() asm volatile("cp.async.commit_group;" ::: "memory")

// ---------------- prep: fp32 -> fp16 elementwise ----------------
__global__ void tohalf_kernel(const float* __restrict__ x, __half* __restrict__ o, int n4) {
    int i = blockIdx.x * blockDim.x + threadIdx.x;
    if (i >= n4) return;
    float4 v = reinterpret_cast<const float4*>(x)[i];
    __half2* o2 = reinterpret_cast<__half2*>(o);
    o2[i * 2 + 0] = __floats2half2_rn(v.x, v.y);
    o2[i * 2 + 1] = __floats2half2_rn(v.z, v.w);
}

// ---------------- gate: exact fp32 ----------------
__global__ void gate_kernel(const float* __restrict__ x, const float* __restrict__ gw,
                            const float* __restrict__ gb,
                            int* __restrict__ topi, float* __restrict__ wts) {
    int t = (blockIdx.x * blockDim.x + threadIdx.x) >> 5;
    int lane = threadIdx.x & 31;
    if (t >= NTOK) return;
    const float* xr = x + (size_t)t * DDIM;
    float s[NEXP];
#pragma unroll
    for (int e = 0; e < NEXP; e++) s[e] = 0.f;
    for (int i = lane; i < DDIM; i += 32) {
        float xv = xr[i];
        const float4* w4 = reinterpret_cast<const float4*>(gw + (size_t)i * NEXP);
#pragma unroll
        for (int q = 0; q < 4; q++) {
            float4 w = w4[q];
            s[q*4+0] += xv * w.x; s[q*4+1] += xv * w.y;
            s[q*4+2] += xv * w.z; s[q*4+3] += xv * w.w;
        }
    }
#pragma unroll
    for (int e = 0; e < NEXP; e++)
#pragma unroll
        for (int off = 16; off > 0; off >>= 1)
            s[e] += __shfl_xor_sync(0xffffffffu, s[e], off);
    if (lane == 0) {
        float mx = s[0];
#pragma unroll
        for (int e = 1; e < NEXP; e++) mx = fmaxf(mx, s[e]);
        float sum = 0.f, sc[NEXP];
#pragma unroll
        for (int e = 0; e < NEXP; e++) { sc[e] = expf(s[e] - mx); sum += sc[e]; }
        float inv = 1.f / sum;
#pragma unroll
        for (int e = 0; e < NEXP; e++) sc[e] = sc[e] * inv + gb[e];
        int i0 = 0; float v0 = sc[0];
#pragma unroll
        for (int e = 1; e < NEXP; e++) if (sc[e] > v0) { v0 = sc[e]; i0 = e; }
        int i1 = 0; float v1 = -1e30f;
#pragma unroll
        for (int e = 0; e < NEXP; e++) if (e != i0 && sc[e] > v1) { v1 = sc[e]; i1 = e; }
        topi[t*2+0] = i0; topi[t*2+1] = i1;
        wts [t*2+0] = s[i0]; wts[t*2+1] = s[i1];
    }
}

__global__ void assign_kernel(const int* __restrict__ topi, const float* __restrict__ wts,
                              int* __restrict__ cnt, int* __restrict__ tokl,
                              float* __restrict__ wl) {
    int i = blockIdx.x * blockDim.x + threadIdx.x;
    if (i >= NTOK * 2) return;
    int e = topi[i];
    int p = atomicAdd(&cnt[e], 1);
    tokl[(size_t)e * NTOK + p] = i >> 1;
    wl  [(size_t)e * NTOK + p] = wts[i];
}

__device__ __forceinline__ unsigned fkey(float f) {
    unsigned u = __float_as_uint(f);
    return (u & 0x80000000u) ? ~u : (u | 0x80000000u);
}

// selection + inverse position map: pos[token*2 + which] = e*CAP + slot
__global__ void select_kernel(const int* __restrict__ cnt, const int* __restrict__ tokl,
                              const float* __restrict__ wl, const int* __restrict__ topi,
                              int* __restrict__ ktok, float* __restrict__ kw,
                              int* __restrict__ mk, int* __restrict__ pos) {
    int e = blockIdx.x;
    int n = cnt[e];
    const int*   tl = tokl + (size_t)e * NTOK;
    const float* wv = wl   + (size_t)e * NTOK;
    int tid = threadIdx.x;

    if (n <= CAP) {
        for (int i = tid; i < n; i += blockDim.x) {
            int tkn = tl[i];
            ktok[(size_t)e * CAP + i] = tkn;
            kw  [(size_t)e * CAP + i] = wv[i];
            int which = (topi[tkn * 2] == e) ? 0 : 1;
            pos[tkn * 2 + which] = e * CAP + i;
        }
        if (tid == 0) mk[e] = n;
        return;
    }
    __shared__ int hist[256];
    __shared__ unsigned s_prefix;
    __shared__ int s_rem, s_nk, s_neq;
    __shared__ int eq_tok[2048];
    __shared__ int eq_src[2048];
    if (tid == 0) { s_prefix = 0u; s_rem = CAP; }
    __syncthreads();
    for (int shift = 24; shift >= 0; shift -= 8) {
        for (int b = tid; b < 256; b += blockDim.x) hist[b] = 0;
        __syncthreads();
        unsigned pfx = s_prefix;
        for (int i = tid; i < n; i += blockDim.x) {
            unsigned key = fkey(wv[i]);
            if (shift == 24 || (key >> (shift + 8)) == pfx)
                atomicAdd(&hist[(key >> shift) & 255], 1);
        }
        __syncthreads();
        if (tid == 0) {
            int rem = s_rem;
            int b = 255;
            for (; b > 0; b--) { if (hist[b] >= rem) break; rem -= hist[b]; }
            s_prefix = (pfx << 8) | (unsigned)b;
            s_rem = rem;
        }
        __syncthreads();
    }
    unsigned T = s_prefix;
    int rem = s_rem;
    if (tid == 0) { s_nk = 0; s_neq = 0; }
    __syncthreads();
    for (int i = tid; i < n; i += blockDim.x) {
        unsigned key = fkey(wv[i]);
        if (key > T) {
            int p = atomicAdd(&s_nk, 1);
            int tkn = tl[i];
            ktok[(size_t)e * CAP + p] = tkn;
            kw  [(size_t)e * CAP + p] = wv[i];
            int which = (topi[tkn * 2] == e) ? 0 : 1;
            pos[tkn * 2 + which] = e * CAP + p;
        } else if (key == T) {
            int p = atomicAdd(&s_neq, 1);
            if (p < 2048) { eq_tok[p] = tl[i]; eq_src[p] = i; }
        }
    }
    __syncthreads();
    int neq = min(s_neq, 2048);
    for (int j = tid; j < neq; j += blockDim.x) {
        int tj = eq_tok[j];
        int rank = 0;
        for (int l = 0; l < neq; l++) rank += (eq_tok[l] < tj);
        if (rank < rem) {
            int p = atomicAdd(&s_nk, 1);
            ktok[(size_t)e * CAP + p] = tj;
            kw  [(size_t)e * CAP + p] = wv[eq_src[j]];
            int which = (topi[tj * 2] == e) ? 0 : 1;
            pos[tj * 2 + which] = e * CAP + p;
        }
    }
    __syncthreads();
    if (tid == 0) mk[e] = s_nk;
}

// ---------------- fp16 mma.sync GEMM: C[M,N] = A[M,K] @ B[K,N] ----------------
// CTA 128x128, 8 warps (warp grid 2m x 4n, warp tile 64x32), KC=64,
// double-buffered cp.async, ldmatrix fragment loads, 2 CTAs/SM.
// MODE 0: C(half)=acc   MODE 1: C(half)=silu(acc)*U   MODE 2: C(float)=acc*scale
// MODE 3: C(half)=acc*roww[r]*scale
template<int MODE, bool GATHER>
__global__ void __launch_bounds__(256, 2)
gemm_h(const __half* __restrict__ A, size_t sAz, int lda,
       const __half* __restrict__ B, size_t sBz,
       void* __restrict__ Cv, size_t sCz, int ldc,
       const __half* __restrict__ U, size_t sUz,
       const int* __restrict__ mlist, int Mmax, int N, int K,
       const int* __restrict__ gidx, const float* __restrict__ roww,
       float outscale)
{
    extern __shared__ char smem[];
    int z = blockIdx.z;
    int M = mlist ? mlist[z] : Mmax;
    int row0 = blockIdx.y * BM;
    if (row0 >= M) return;
    int col0 = blockIdx.x * BN;

    A += sAz * z;
    B += sBz * z;
    if (MODE == 1) U += sUz * z;
    const int*   gl = gidx ? gidx + (size_t)z * CAP : nullptr;
    const float* rw = roww ? roww + (size_t)z * CAP : nullptr;
    __half* Ch = (__half*)Cv + sCz * z;
    float*  Cf = (float*)Cv;

    int tid = threadIdx.x;
    int lane = tid & 31, wid = tid >> 5;
    int wm = wid >> 2, wn = wid & 3;          // warp tile 64x32
    int g = lane >> 2, t4 = lane & 3;

    // --- staging: A row = tid>>1 (2 threads/row, 64B each); B row = tid>>2 (4/row, 64B) ---
    int arow = tid >> 1, aseg = tid & 1;
    const __half* aptr = A;
    int asz = 0;
    {
        int r = row0 + arow;
        if (r < M) {
            int gr = GATHER ? gl[r] : r;
            aptr = A + (size_t)gr * lda + aseg * 32;
            asz = 16;
        }
    }
    int bkrow = tid >> 2, bseg = tid & 3;
    const __half* bptr = B + (size_t)bkrow * N + col0 + bseg * 32;
    uint32_t sbase = (uint32_t)__cvta_generic_to_shared(smem);
    uint32_t aoff = (uint32_t)arow * A_ROWB + (uint32_t)aseg * 64;
    uint32_t boff = (uint32_t)A_BYTES + (uint32_t)bkrow * B_ROWB + (uint32_t)bseg * 64;

    // --- ldmatrix lane addresses (buffer-relative) ---
    uint32_t a_lm = (uint32_t)(wm * 64 + (lane & 15)) * A_ROWB + (uint32_t)(lane >> 4) * 16;
    uint32_t b_lm = (uint32_t)A_BYTES
                  + (uint32_t)((((lane >> 3) & 1) * 8 + (lane & 7))) * B_ROWB
                  + (uint32_t)(wn * 32 + (lane >> 4) * 8) * 2;

    float acc[4][4][4];
#pragma unroll
    for (int mt = 0; mt < 4; mt++)
#pragma unroll
        for (int nt = 0; nt < 4; nt++)
#pragma unroll
            for (int q = 0; q < 4; q++) acc[mt][nt][q] = 0.f;

    int nk = K / KC;
    {   // prologue -> buf0
        uint32_t dA = sbase + aoff;
        uint32_t dB = sbase + boff;
#pragma unroll
        for (int c = 0; c < 4; c++) cpasync16(dA + c * 16, aptr + c * 8, asz);
#pragma unroll
        for (int c = 0; c < 4; c++) cpasync16(dB + c * 16, bptr + c * 8, 16);
        CP_COMMIT();
    }

    for (int kb = 0; kb < nk; kb++) {
        if (kb + 1 < nk) {
            uint32_t bs = ((kb + 1) & 1) * BUF_BYTES;
            const __half* as = aptr + (kb + 1) * KC;
            const __half* bsrc = bptr + (size_t)(kb + 1) * KC * N;
            uint32_t dA = sbase + bs + aoff;
            uint32_t dB = sbase + bs + boff;
#pragma unroll
            for (int c = 0; c < 4; c++) cpasync16(dA + c * 16, as + c * 8, asz);
#pragma unroll
            for (int c = 0; c < 4; c++) cpasync16(dB + c * 16, bsrc + c * 8, 16);
            CP_COMMIT();
            asm volatile("cp.async.wait_group 1;" ::: "memory");
        } else {
            asm volatile("cp.async.wait_group 0;" ::: "memory");
        }
        __syncthreads();

        uint32_t bufb = sbase + (kb & 1) * BUF_BYTES;
#pragma unroll
        for (int ks = 0; ks < 4; ks++) {
            uint32_t af[4][4], bf[4][2];
#pragma unroll
            for (int mt = 0; mt < 4; mt++) {
                uint32_t ad = bufb + a_lm + (uint32_t)mt * (16 * A_ROWB) + (uint32_t)ks * 32;
                asm volatile("ldmatrix.sync.aligned.m8n8.x4.shared.b16 {%0,%1,%2,%3}, [%4];"
                             : "=r"(af[mt][0]), "=r"(af[mt][1]), "=r"(af[mt][2]), "=r"(af[mt][3])
                             : "r"(ad));
            }
#pragma unroll
            for (int p = 0; p < 2; p++) {
                uint32_t bd = bufb + b_lm + (uint32_t)ks * (16 * B_ROWB) + (uint32_t)p * 32;
                asm volatile("ldmatrix.sync.aligned.m8n8.x4.trans.shared.b16 {%0,%1,%2,%3}, [%4];"
                             : "=r"(bf[2*p][0]), "=r"(bf[2*p][1]),
                               "=r"(bf[2*p+1][0]), "=r"(bf[2*p+1][1])
                             : "r"(bd));
            }
#pragma unroll
            for (int mt = 0; mt < 4; mt++)
#pragma unroll
                for (int nt = 0; nt < 4; nt++)
                    asm volatile(
                        "mma.sync.aligned.m16n8k16.row.col.f32.f16.f16.f32 "
                        "{%0,%1,%2,%3}, {%4,%5,%6,%7}, {%8,%9}, {%0,%1,%2,%3};"
                        : "+f"(acc[mt][nt][0]), "+f"(acc[mt][nt][1]),
                          "+f"(acc[mt][nt][2]), "+f"(acc[mt][nt][3])
                        : "r"(af[mt][0]), "r"(af[mt][1]), "r"(af[mt][2]), "r"(af[mt][3]),
                          "r"(bf[nt][0]), "r"(bf[nt][1]));
        }
        __syncthreads();
    }

    // ---------------- epilogue ----------------
#pragma unroll
    for (int mt = 0; mt < 4; mt++) {
#pragma unroll
        for (int h = 0; h < 2; h++) {
            int rr = row0 + wm * 64 + mt * 16 + g + h * 8;
            if (rr >= M) continue;
            float scl = outscale;
            if (MODE == 3) scl = rw[rr] * outscale;
#pragma unroll
            for (int nt = 0; nt < 4; nt++) {
                int cc = col0 + wn * 32 + nt * 8 + t4 * 2;
                float v0 = acc[mt][nt][h * 2 + 0];
                float v1 = acc[mt][nt][h * 2 + 1];
                size_t off = (size_t)rr * ldc + cc;
                if (MODE == 0) {
                    *reinterpret_cast<__half2*>(Ch + off) = __floats2half2_rn(v0, v1);
                } else if (MODE == 1) {
                    __half2 u2 = *reinterpret_cast<const __half2*>(U + off);
                    float s0 = v0 / (1.f + __expf(-v0));
                    float s1 = v1 / (1.f + __expf(-v1));
                    *reinterpret_cast<__half2*>(Ch + off) =
                        __floats2half2_rn(s0 * __low2float(u2), s1 * __high2float(u2));
                } else if (MODE == 2) {
                    float2 v = make_float2(v0 * outscale, v1 * outscale);
                    *reinterpret_cast<float2*>(Cf + off) = v;
                } else { // MODE 3
                    *reinterpret_cast<__half2*>(Ch + off) = __floats2half2_rn(v0 * scl, v1 * scl);
                }
            }
        }
    }
}

// ---------------- final combine: out[t] += y[pos0] + y[pos1] ----------------
__global__ void combine_kernel(const int* __restrict__ pos, const __half* __restrict__ y,
                               float* __restrict__ out) {
    int i = blockIdx.x * blockDim.x + threadIdx.x;
    int tok = i >> 8;
    int c = (i & 255) * 4;
    int p0 = pos[tok * 2], p1 = pos[tok * 2 + 1];
    float4 o = *reinterpret_cast<float4*>(out + (size_t)tok * DDIM + c);
    if (p0 >= 0) {
        __half2 a = *reinterpret_cast<const __half2*>(y + (size_t)p0 * DDIM + c);
        __half2 b = *reinterpret_cast<const __half2*>(y + (size_t)p0 * DDIM + c + 2);
        o.x += __low2float(a); o.y += __high2float(a);
        o.z += __low2float(b); o.w += __high2float(b);
    }
    if (p1 >= 0) {
        __half2 a = *reinterpret_cast<const __half2*>(y + (size_t)p1 * DDIM + c);
        __half2 b = *reinterpret_cast<const __half2*>(y + (size_t)p1 * DDIM + c + 2);
        o.x += __low2float(a); o.y += __high2float(a);
        o.z += __low2float(b); o.w += __high2float(b);
    }
    *reinterpret_cast<float4*>(out + (size_t)tok * DDIM + c) = o;
}

// ---------------- host launcher ----------------
extern "C" void kernel_launch(void* const* d_in, const int* in_sizes, int n_in,
                              void* d_out, int out_size) {
    const float* x   = (const float*)d_in[0];
    const float* gw  = (const float*)d_in[1];
    const float* gb  = (const float*)d_in[2];
    const float* ew1 = (const float*)d_in[3];
    const float* ew3 = (const float*)d_in[4];
    const float* ew2 = (const float*)d_in[5];
    const float* sw1 = (const float*)d_in[6];
    const float* sw3 = (const float*)d_in[7];
    const float* sw2 = (const float*)d_in[8];
    float* out = (float*)d_out;

    __half *ubuf, *act, *hx, *w1h, *w3h, *w2h, *sw1h, *sw3h, *sw2h;
    float *wts, *wl, *kw;
    int *topi, *cnt, *tokl, *ktok, *mk, *pos;
    cudaGetSymbolAddress((void**)&ubuf, g_ubuf);
    cudaGetSymbolAddress((void**)&act,  g_act);
    cudaGetSymbolAddress((void**)&hx,   g_hx);
    cudaGetSymbolAddress((void**)&w1h,  g_w1h);
    cudaGetSymbolAddress((void**)&w3h,  g_w3h);
    cudaGetSymbolAddress((void**)&w2h,  g_w2h);
    cudaGetSymbolAddress((void**)&sw1h, g_sw1h);
    cudaGetSymbolAddress((void**)&sw3h, g_sw3h);
    cudaGetSymbolAddress((void**)&sw2h, g_sw2h);
    cudaGetSymbolAddress((void**)&topi, g_topi);
    cudaGetSymbolAddress((void**)&wts,  g_wts);
    cudaGetSymbolAddress((void**)&cnt,  g_cnt);
    cudaGetSymbolAddress((void**)&tokl, g_tokl);
    cudaGetSymbolAddress((void**)&wl,   g_wl);
    cudaGetSymbolAddress((void**)&ktok, g_ktok);
    cudaGetSymbolAddress((void**)&kw,   g_kw);
    cudaGetSymbolAddress((void**)&mk,   g_mk);
    cudaGetSymbolAddress((void**)&pos,  g_pos);

    cudaFuncSetAttribute((const void*)gemm_h<0,false>, cudaFuncAttributeMaxDynamicSharedMemorySize, SMEM_BYTES);
    cudaFuncSetAttribute((const void*)gemm_h<1,false>, cudaFuncAttributeMaxDynamicSharedMemorySize, SMEM_BYTES);
    cudaFuncSetAttribute((const void*)gemm_h<2,false>, cudaFuncAttributeMaxDynamicSharedMemorySize, SMEM_BYTES);
    cudaFuncSetAttribute((const void*)gemm_h<0,true>,  cudaFuncAttributeMaxDynamicSharedMemorySize, SMEM_BYTES);
    cudaFuncSetAttribute((const void*)gemm_h<1,true>,  cudaFuncAttributeMaxDynamicSharedMemorySize, SMEM_BYTES);
    cudaFuncSetAttribute((const void*)gemm_h<3,false>, cudaFuncAttributeMaxDynamicSharedMemorySize, SMEM_BYTES);

    cudaMemsetAsync(cnt, 0, NEXP * sizeof(int), 0);
    cudaMemsetAsync(pos, 0xFF, NTOK * 2 * sizeof(int), 0);

    // prep: fp16 conversions (weights keep natural K-major layout)
    tohalf_kernel<<<(NTOK*DDIM/4 + 255)/256, 256>>>(x, hx, NTOK*DDIM/4);
    int we4 = NEXP*DDIM*HDIM/4;
    tohalf_kernel<<<(we4 + 255)/256, 256>>>(ew1, w1h, we4);
    tohalf_kernel<<<(we4 + 255)/256, 256>>>(ew3, w3h, we4);
    tohalf_kernel<<<(we4 + 255)/256, 256>>>(ew2, w2h, we4);
    int ws4 = 2*DDIM*HDIM/4;
    tohalf_kernel<<<(ws4 + 255)/256, 256>>>(sw1, sw1h, ws4);
    tohalf_kernel<<<(ws4 + 255)/256, 256>>>(sw3, sw3h, ws4);
    tohalf_kernel<<<(ws4 + 255)/256, 256>>>(sw2, sw2h, ws4);

    // routing (exact fp32)
    gate_kernel<<<NTOK / 8, 256>>>(x, gw, gb, topi, wts);
    assign_kernel<<<(NTOK * 2 + 255) / 256, 256>>>(topi, wts, cnt, tokl, wl);
    select_kernel<<<NEXP, 256>>>(cnt, tokl, wl, topi, ktok, kw, mk, pos);

    // ---- shared experts: u/act staged K-concat [NTOK][2*HDIM] ----
    gemm_h<0,false><<<dim3(HDIM/BN, NTOK/BM, 2), 256, SMEM_BYTES>>>(
        hx, 0, DDIM, sw3h, (size_t)DDIM*HDIM, ubuf, (size_t)HDIM, 2*HDIM,
        nullptr, 0, nullptr, NTOK, HDIM, DDIM, nullptr, nullptr, 1.f);
    gemm_h<1,false><<<dim3(HDIM/BN, NTOK/BM, 2), 256, SMEM_BYTES>>>(
        hx, 0, DDIM, sw1h, (size_t)DDIM*HDIM, act, (size_t)HDIM, 2*HDIM,
        ubuf, (size_t)HDIM, nullptr, NTOK, HDIM, DDIM, nullptr, nullptr, 1.f);
    // both shared down-projs as ONE K=4096 GEMM; writes ALL of out (fp32)
    gemm_h<2,false><<<dim3(DDIM/BN, NTOK/BM, 1), 256, SMEM_BYTES>>>(
        act, 0, 2*HDIM, sw2h, 0, out, 0, DDIM,
        nullptr, 0, nullptr, NTOK, DDIM, 2*HDIM, nullptr, nullptr, 0.5f);

    // ---- routed experts ----
    gemm_h<0,true><<<dim3(HDIM/BN, (CAP+BM-1)/BM, NEXP), 256, SMEM_BYTES>>>(
        hx, 0, DDIM, w3h, (size_t)DDIM*HDIM, ubuf, (size_t)CAP*HDIM, HDIM,
        nullptr, 0, mk, CAP, HDIM, DDIM, ktok, nullptr, 1.f);
    gemm_h<1,true><<<dim3(HDIM/BN, (CAP+BM-1)/BM, NEXP), 256, SMEM_BYTES>>>(
        hx, 0, DDIM, w1h, (size_t)DDIM*HDIM, act, (size_t)CAP*HDIM, HDIM,
        ubuf, (size_t)CAP*HDIM, mk, CAP, HDIM, DDIM, ktok, nullptr, 1.f);
    // routed down-proj: weighted direct store into y staging (reuses g_ubuf)
    gemm_h<3,false><<<dim3(DDIM/BN, (CAP+BM-1)/BM, NEXP), 256, SMEM_BYTES>>>(
        act, (size_t)CAP*HDIM, HDIM, w2h, (size_t)HDIM*DDIM, ubuf, (size_t)CAP*DDIM, DDIM,
        nullptr, 0, mk, CAP, DDIM, HDIM, nullptr, kw, 1.f);

    // final gather-sum (no atomics)
    combine_kernel<<<NTOK * 256 / 256, 256>>>(pos, ubuf, out);
}

// round 7
// speedup vs baseline: 1.6121x; 1.0287x over previous
#include <cuda_runtime.h>
#include <cuda_fp16.h>
#include <cstdint>

#define NTOK 16384
#define DDIM 1024
#define HDIM 2048
#define NEXP 16
#define CAP  2560
#define BM 128
#define BN 128
#define KC 64
#define A_ROWB 144                   // 64 halves + 8 pad, bytes
#define B_ROWB 272                   // 128 halves + 8 pad, bytes
#define A_BYTES (BM * A_ROWB)        // 18432
#define B_BYTES (KC * B_ROWB)        // 17408
#define BUF_BYTES (A_BYTES + B_BYTES)
#define NSTAGE 3
#define SMEM_BYTES (NSTAGE * BUF_BYTES)  // 107520 -> 2 CTAs/SM

// ---------------- scratch (device globals; no allocation) ----------------
__device__ __half g_act  [(size_t)NEXP * CAP * HDIM];       // act (shared phase: [NTOK][2H])
__device__ __half g_y    [(size_t)NEXP * CAP * DDIM];       // routed y staging
__device__ __half g_hx   [(size_t)NTOK * DDIM];
__device__ __half g_wg   [(size_t)NEXP * DDIM * 2 * HDIM];  // interleaved w1/w3
__device__ __half g_swg  [(size_t)2 * DDIM * 2 * HDIM];     // interleaved sw1/sw3
__device__ __half g_w2h  [(size_t)NEXP * HDIM * DDIM];
__device__ __half g_sw2h [(size_t)2 * HDIM * DDIM];
__device__ int    g_topi[NTOK * 2];
__device__ float  g_wts [NTOK * 2];
__device__ int    g_cnt [NEXP];
__device__ int    g_tokl[NEXP * NTOK];
__device__ float  g_wl  [NEXP * NTOK];
__device__ int    g_ktok[NEXP * CAP];
__device__ float  g_kw  [NEXP * CAP];
__device__ int    g_mk  [NEXP];
__device__ int    g_pos [NTOK * 2];

// ---------------- helpers ----------------
__device__ __forceinline__ void cpasync16(uint32_t dst, const void* src, int srcsz) {
    asm volatile("cp.async.cg.shared.global [%0], [%1], 16, %2;"
                 :: "r"(dst), "l"(src), "r"(srcsz));
}
#define CP_COMMIT() asm volatile("cp.async.commit_group;" ::: "memory")

// ---------------- prep kernels ----------------
__global__ void tohalf_kernel(const float* __restrict__ x, __half* __restrict__ o, int n4) {
    int i = blockIdx.x * blockDim.x + threadIdx.x;
    if (i >= n4) return;
    float4 v = reinterpret_cast<const float4*>(x)[i];
    __half2* o2 = reinterpret_cast<__half2*>(o);
    o2[i * 2 + 0] = __floats2half2_rn(v.x, v.y);
    o2[i * 2 + 1] = __floats2half2_rn(v.z, v.w);
}

// interleave columns of w1/w3: wg[.., 2j]=w1[..,j], wg[.., 2j+1]=w3[..,j]
__global__ void interleave_kernel(const float* __restrict__ w1, const float* __restrict__ w3,
                                  __half* __restrict__ wg, int n4) {
    int i = blockIdx.x * blockDim.x + threadIdx.x;
    if (i >= n4) return;
    float4 a = reinterpret_cast<const float4*>(w1)[i];
    float4 b = reinterpret_cast<const float4*>(w3)[i];
    __half2 h0 = __floats2half2_rn(a.x, b.x);
    __half2 h1 = __floats2half2_rn(a.y, b.y);
    __half2 h2 = __floats2half2_rn(a.z, b.z);
    __half2 h3 = __floats2half2_rn(a.w, b.w);
    uint4 o;
    o.x = *reinterpret_cast<uint32_t*>(&h0);
    o.y = *reinterpret_cast<uint32_t*>(&h1);
    o.z = *reinterpret_cast<uint32_t*>(&h2);
    o.w = *reinterpret_cast<uint32_t*>(&h3);
    reinterpret_cast<uint4*>(wg)[i] = o;
}

// ---------------- gate: exact fp32 ----------------
__global__ void gate_kernel(const float* __restrict__ x, const float* __restrict__ gw,
                            const float* __restrict__ gb,
                            int* __restrict__ topi, float* __restrict__ wts) {
    int t = (blockIdx.x * blockDim.x + threadIdx.x) >> 5;
    int lane = threadIdx.x & 31;
    if (t >= NTOK) return;
    const float* xr = x + (size_t)t * DDIM;
    float s[NEXP];
#pragma unroll
    for (int e = 0; e < NEXP; e++) s[e] = 0.f;
    for (int i = lane; i < DDIM; i += 32) {
        float xv = xr[i];
        const float4* w4 = reinterpret_cast<const float4*>(gw + (size_t)i * NEXP);
#pragma unroll
        for (int q = 0; q < 4; q++) {
            float4 w = w4[q];
            s[q*4+0] += xv * w.x; s[q*4+1] += xv * w.y;
            s[q*4+2] += xv * w.z; s[q*4+3] += xv * w.w;
        }
    }
#pragma unroll
    for (int e = 0; e < NEXP; e++)
#pragma unroll
        for (int off = 16; off > 0; off >>= 1)
            s[e] += __shfl_xor_sync(0xffffffffu, s[e], off);
    if (lane == 0) {
        float mx = s[0];
#pragma unroll
        for (int e = 1; e < NEXP; e++) mx = fmaxf(mx, s[e]);
        float sum = 0.f, sc[NEXP];
#pragma unroll
        for (int e = 0; e < NEXP; e++) { sc[e] = expf(s[e] - mx); sum += sc[e]; }
        float inv = 1.f / sum;
#pragma unroll
        for (int e = 0; e < NEXP; e++) sc[e] = sc[e] * inv + gb[e];
        int i0 = 0; float v0 = sc[0];
#pragma unroll
        for (int e = 1; e < NEXP; e++) if (sc[e] > v0) { v0 = sc[e]; i0 = e; }
        int i1 = 0; float v1 = -1e30f;
#pragma unroll
        for (int e = 0; e < NEXP; e++) if (e != i0 && sc[e] > v1) { v1 = sc[e]; i1 = e; }
        topi[t*2+0] = i0; topi[t*2+1] = i1;
        wts [t*2+0] = s[i0]; wts[t*2+1] = s[i1];
    }
}

__global__ void assign_kernel(const int* __restrict__ topi, const float* __restrict__ wts,
                              int* __restrict__ cnt, int* __restrict__ tokl,
                              float* __restrict__ wl) {
    int i = blockIdx.x * blockDim.x + threadIdx.x;
    if (i >= NTOK * 2) return;
    int e = topi[i];
    int p = atomicAdd(&cnt[e], 1);
    tokl[(size_t)e * NTOK + p] = i >> 1;
    wl  [(size_t)e * NTOK + p] = wts[i];
}

__device__ __forceinline__ unsigned fkey(float f) {
    unsigned u = __float_as_uint(f);
    return (u & 0x80000000u) ? ~u : (u | 0x80000000u);
}

// selection + inverse position map: pos[token*2 + which] = e*CAP + slot
__global__ void select_kernel(const int* __restrict__ cnt, const int* __restrict__ tokl,
                              const float* __restrict__ wl, const int* __restrict__ topi,
                              int* __restrict__ ktok, float* __restrict__ kw,
                              int* __restrict__ mk, int* __restrict__ pos) {
    int e = blockIdx.x;
    int n = cnt[e];
    const int*   tl = tokl + (size_t)e * NTOK;
    const float* wv = wl   + (size_t)e * NTOK;
    int tid = threadIdx.x;

    if (n <= CAP) {
        for (int i = tid; i < n; i += blockDim.x) {
            int tkn = tl[i];
            ktok[(size_t)e * CAP + i] = tkn;
            kw  [(size_t)e * CAP + i] = wv[i];
            int which = (topi[tkn * 2] == e) ? 0 : 1;
            pos[tkn * 2 + which] = e * CAP + i;
        }
        if (tid == 0) mk[e] = n;
        return;
    }
    __shared__ int hist[256];
    __shared__ unsigned s_prefix;
    __shared__ int s_rem, s_nk, s_neq;
    __shared__ int eq_tok[2048];
    __shared__ int eq_src[2048];
    if (tid == 0) { s_prefix = 0u; s_rem = CAP; }
    __syncthreads();
    for (int shift = 24; shift >= 0; shift -= 8) {
        for (int b = tid; b < 256; b += blockDim.x) hist[b] = 0;
        __syncthreads();
        unsigned pfx = s_prefix;
        for (int i = tid; i < n; i += blockDim.x) {
            unsigned key = fkey(wv[i]);
            if (shift == 24 || (key >> (shift + 8)) == pfx)
                atomicAdd(&hist[(key >> shift) & 255], 1);
        }
        __syncthreads();
        if (tid == 0) {
            int rem = s_rem;
            int b = 255;
            for (; b > 0; b--) { if (hist[b] >= rem) break; rem -= hist[b]; }
            s_prefix = (pfx << 8) | (unsigned)b;
            s_rem = rem;
        }
        __syncthreads();
    }
    unsigned T = s_prefix;
    int rem = s_rem;
    if (tid == 0) { s_nk = 0; s_neq = 0; }
    __syncthreads();
    for (int i = tid; i < n; i += blockDim.x) {
        unsigned key = fkey(wv[i]);
        if (key > T) {
            int p = atomicAdd(&s_nk, 1);
            int tkn = tl[i];
            ktok[(size_t)e * CAP + p] = tkn;
            kw  [(size_t)e * CAP + p] = wv[i];
            int which = (topi[tkn * 2] == e) ? 0 : 1;
            pos[tkn * 2 + which] = e * CAP + p;
        } else if (key == T) {
            int p = atomicAdd(&s_neq, 1);
            if (p < 2048) { eq_tok[p] = tl[i]; eq_src[p] = i; }
        }
    }
    __syncthreads();
    int neq = min(s_neq, 2048);
    for (int j = tid; j < neq; j += blockDim.x) {
        int tj = eq_tok[j];
        int rank = 0;
        for (int l = 0; l < neq; l++) rank += (eq_tok[l] < tj);
        if (rank < rem) {
            int p = atomicAdd(&s_nk, 1);
            ktok[(size_t)e * CAP + p] = tj;
            kw  [(size_t)e * CAP + p] = wv[eq_src[j]];
            int which = (topi[tj * 2] == e) ? 0 : 1;
            pos[tj * 2 + which] = e * CAP + p;
        }
    }
    __syncthreads();
    if (tid == 0) mk[e] = s_nk;
}

// ---------------- fp16 mma.sync GEMM: C = A[M,K] @ B[K,N] ----------------
// CTA 128x128, 8 warps (2m x 4n, warp tile 64x32), KC=64,
// 3-stage cp.async pipeline (ONE __syncthreads per k-iter), 2 CTAs/SM.
// MODE 2: C(float)[r][c] = acc*scale
// MODE 3: C(half) [r][c] = acc*roww[r]*scale
// MODE 5: fused SwiGLU: B interleaved (w1|w3); C(half)[r][c/2] = silu(v0)*v1
template<int MODE, bool GATHER>
__global__ void __launch_bounds__(256, 2)
gemm_h(const __half* __restrict__ A, size_t sAz, int lda,
       const __half* __restrict__ B, size_t sBz,
       void* __restrict__ Cv, size_t sCz, int ldc,
       const int* __restrict__ mlist, int Mmax, int N, int K,
       const int* __restrict__ gidx, const float* __restrict__ roww,
       float outscale)
{
    extern __shared__ char smem[];
    int z = blockIdx.z;
    int M = mlist ? mlist[z] : Mmax;
    int row0 = blockIdx.y * BM;
    if (row0 >= M) return;
    int col0 = blockIdx.x * BN;

    A += sAz * z;
    B += sBz * z;
    const int*   gl = gidx ? gidx + (size_t)z * CAP : nullptr;
    const float* rw = roww ? roww + (size_t)z * CAP : nullptr;
    __half* Ch = (__half*)Cv + sCz * z;
    float*  Cf = (float*)Cv;

    int tid = threadIdx.x;
    int lane = tid & 31, wid = tid >> 5;
    int wm = wid >> 2, wn = wid & 3;          // warp tile 64x32
    int g = lane >> 2, t4 = lane & 3;

    // staging: A row = tid>>1 (2 threads/row, 64B each); B row = tid>>2 (4/row, 64B)
    int arow = tid >> 1, aseg = tid & 1;
    const __half* aptr = A;
    int asz = 0;
    {
        int r = row0 + arow;
        if (r < M) {
            int gr = GATHER ? gl[r] : r;
            aptr = A + (size_t)gr * lda + aseg * 32;
            asz = 16;
        }
    }
    int bkrow = tid >> 2, bseg = tid & 3;
    const __half* bptr = B + (size_t)bkrow * N + col0 + bseg * 32;
    uint32_t sbase = (uint32_t)__cvta_generic_to_shared(smem);
    uint32_t aoff = (uint32_t)arow * A_ROWB + (uint32_t)aseg * 64;
    uint32_t boff = (uint32_t)A_BYTES + (uint32_t)bkrow * B_ROWB + (uint32_t)bseg * 64;

    // ldmatrix lane addresses (buffer-relative)
    uint32_t a_lm = (uint32_t)(wm * 64 + (lane & 15)) * A_ROWB + (uint32_t)(lane >> 4) * 16;
    uint32_t b_lm = (uint32_t)A_BYTES
                  + (uint32_t)((((lane >> 3) & 1) * 8 + (lane & 7))) * B_ROWB
                  + (uint32_t)(wn * 32 + (lane >> 4) * 8) * 2;

    float acc[4][4][4];
#pragma unroll
    for (int mt = 0; mt < 4; mt++)
#pragma unroll
        for (int nt = 0; nt < 4; nt++)
#pragma unroll
            for (int q = 0; q < 4; q++) acc[mt][nt][q] = 0.f;

    int nk = K / KC;

#define ISSUE_STAGE(KB) do { \
    uint32_t bs_ = (uint32_t)((KB) % NSTAGE) * BUF_BYTES; \
    const __half* as_ = aptr + (KB) * KC; \
    const __half* bs2_ = bptr + (size_t)(KB) * KC * N; \
    uint32_t dA_ = sbase + bs_ + aoff; \
    uint32_t dB_ = sbase + bs_ + boff; \
    _Pragma("unroll") \
    for (int c_ = 0; c_ < 4; c_++) cpasync16(dA_ + c_ * 16, as_ + c_ * 8, asz); \
    _Pragma("unroll") \
    for (int c_ = 0; c_ < 4; c_++) cpasync16(dB_ + c_ * 16, bs2_ + c_ * 8, 16); \
} while (0)

    ISSUE_STAGE(0); CP_COMMIT();
    ISSUE_STAGE(1); CP_COMMIT();

    for (int kb = 0; kb < nk; kb++) {
        asm volatile("cp.async.wait_group 1;" ::: "memory");
        __syncthreads();
        if (kb + 2 < nk) ISSUE_STAGE(kb + 2);
        CP_COMMIT();

        uint32_t bufb = sbase + (uint32_t)(kb % NSTAGE) * BUF_BYTES;
#pragma unroll
        for (int ks = 0; ks < 4; ks++) {
            uint32_t af[4][4], bf[4][2];
#pragma unroll
            for (int mt = 0; mt < 4; mt++) {
                uint32_t ad = bufb + a_lm + (uint32_t)mt * (16 * A_ROWB) + (uint32_t)ks * 32;
                asm volatile("ldmatrix.sync.aligned.m8n8.x4.shared.b16 {%0,%1,%2,%3}, [%4];"
                             : "=r"(af[mt][0]), "=r"(af[mt][1]), "=r"(af[mt][2]), "=r"(af[mt][3])
                             : "r"(ad));
            }
#pragma unroll
            for (int p = 0; p < 2; p++) {
                uint32_t bd = bufb + b_lm + (uint32_t)ks * (16 * B_ROWB) + (uint32_t)p * 32;
                asm volatile("ldmatrix.sync.aligned.m8n8.x4.trans.shared.b16 {%0,%1,%2,%3}, [%4];"
                             : "=r"(bf[2*p][0]), "=r"(bf[2*p][1]),
                               "=r"(bf[2*p+1][0]), "=r"(bf[2*p+1][1])
                             : "r"(bd));
            }
#pragma unroll
            for (int mt = 0; mt < 4; mt++)
#pragma unroll
                for (int nt = 0; nt < 4; nt++)
                    asm volatile(
                        "mma.sync.aligned.m16n8k16.row.col.f32.f16.f16.f32 "
                        "{%0,%1,%2,%3}, {%4,%5,%6,%7}, {%8,%9}, {%0,%1,%2,%3};"
                        : "+f"(acc[mt][nt][0]), "+f"(acc[mt][nt][1]),
                          "+f"(acc[mt][nt][2]), "+f"(acc[mt][nt][3])
                        : "r"(af[mt][0]), "r"(af[mt][1]), "r"(af[mt][2]), "r"(af[mt][3]),
                          "r"(bf[nt][0]), "r"(bf[nt][1]));
        }
    }
#undef ISSUE_STAGE

    // ---------------- epilogue ----------------
#pragma unroll
    for (int mt = 0; mt < 4; mt++) {
#pragma unroll
        for (int h = 0; h < 2; h++) {
            int rr = row0 + wm * 64 + mt * 16 + g + h * 8;
            if (rr >= M) continue;
            float scl = outscale;
            if (MODE == 3) scl = rw[rr] * outscale;
#pragma unroll
            for (int nt = 0; nt < 4; nt++) {
                int cc = col0 + wn * 32 + nt * 8 + t4 * 2;
                float v0 = acc[mt][nt][h * 2 + 0];
                float v1 = acc[mt][nt][h * 2 + 1];
                if (MODE == 2) {
                    size_t off = (size_t)rr * ldc + cc;
                    float2 v = make_float2(v0 * outscale, v1 * outscale);
                    *reinterpret_cast<float2*>(Cf + off) = v;
                } else if (MODE == 3) {
                    size_t off = (size_t)rr * ldc + cc;
                    *reinterpret_cast<__half2*>(Ch + off) = __floats2half2_rn(v0 * scl, v1 * scl);
                } else { // MODE 5: (v0,v1) = (a1, a3) for hidden unit cc/2
                    float sv = v0 / (1.f + __expf(-v0)) * v1;
                    Ch[(size_t)rr * ldc + (cc >> 1)] = __float2half_rn(sv);
                }
            }
        }
    }
}

// ---------------- final combine: out[t] += y[pos0] + y[pos1] ----------------
__global__ void combine_kernel(const int* __restrict__ pos, const __half* __restrict__ y,
                               float* __restrict__ out) {
    int i = blockIdx.x * blockDim.x + threadIdx.x;
    int tok = i >> 8;
    int c = (i & 255) * 4;
    int p0 = pos[tok * 2], p1 = pos[tok * 2 + 1];
    float4 o = *reinterpret_cast<float4*>(out + (size_t)tok * DDIM + c);
    if (p0 >= 0) {
        __half2 a = *reinterpret_cast<const __half2*>(y + (size_t)p0 * DDIM + c);
        __half2 b = *reinterpret_cast<const __half2*>(y + (size_t)p0 * DDIM + c + 2);
        o.x += __low2float(a); o.y += __high2float(a);
        o.z += __low2float(b); o.w += __high2float(b);
    }
    if (p1 >= 0) {
        __half2 a = *reinterpret_cast<const __half2*>(y + (size_t)p1 * DDIM + c);
        __half2 b = *reinterpret_cast<const __half2*>(y + (size_t)p1 * DDIM + c + 2);
        o.x += __low2float(a); o.y += __high2float(a);
        o.z += __low2float(b); o.w += __high2float(b);
    }
    *reinterpret_cast<float4*>(out + (size_t)tok * DDIM + c) = o;
}

// ---------------- host launcher ----------------
extern "C" void kernel_launch(void* const* d_in, const int* in_sizes, int n_in,
                              void* d_out, int out_size) {
    const float* x   = (const float*)d_in[0];
    const float* gw  = (const float*)d_in[1];
    const float* gb  = (const float*)d_in[2];
    const float* ew1 = (const float*)d_in[3];
    const float* ew3 = (const float*)d_in[4];
    const float* ew2 = (const float*)d_in[5];
    const float* sw1 = (const float*)d_in[6];
    const float* sw3 = (const float*)d_in[7];
    const float* sw2 = (const float*)d_in[8];
    float* out = (float*)d_out;

    __half *act, *yb, *hx, *wg, *swg, *w2h, *sw2h;
    float *wts, *wl, *kw;
    int *topi, *cnt, *tokl, *ktok, *mk, *pos;
    cudaGetSymbolAddress((void**)&act,  g_act);
    cudaGetSymbolAddress((void**)&yb,   g_y);
    cudaGetSymbolAddress((void**)&hx,   g_hx);
    cudaGetSymbolAddress((void**)&wg,   g_wg);
    cudaGetSymbolAddress((void**)&swg,  g_swg);
    cudaGetSymbolAddress((void**)&w2h,  g_w2h);
    cudaGetSymbolAddress((void**)&sw2h, g_sw2h);
    cudaGetSymbolAddress((void**)&topi, g_topi);
    cudaGetSymbolAddress((void**)&wts,  g_wts);
    cudaGetSymbolAddress((void**)&cnt,  g_cnt);
    cudaGetSymbolAddress((void**)&tokl, g_tokl);
    cudaGetSymbolAddress((void**)&wl,   g_wl);
    cudaGetSymbolAddress((void**)&ktok, g_ktok);
    cudaGetSymbolAddress((void**)&kw,   g_kw);
    cudaGetSymbolAddress((void**)&mk,   g_mk);
    cudaGetSymbolAddress((void**)&pos,  g_pos);

    cudaFuncSetAttribute((const void*)gemm_h<5,false>, cudaFuncAttributeMaxDynamicSharedMemorySize, SMEM_BYTES);
    cudaFuncSetAttribute((const void*)gemm_h<5,true>,  cudaFuncAttributeMaxDynamicSharedMemorySize, SMEM_BYTES);
    cudaFuncSetAttribute((const void*)gemm_h<2,false>, cudaFuncAttributeMaxDynamicSharedMemorySize, SMEM_BYTES);
    cudaFuncSetAttribute((const void*)gemm_h<3,false>, cudaFuncAttributeMaxDynamicSharedMemorySize, SMEM_BYTES);

    cudaMemsetAsync(cnt, 0, NEXP * sizeof(int), 0);
    cudaMemsetAsync(pos, 0xFF, NTOK * 2 * sizeof(int), 0);

    // prep: fp16 conversions + w1/w3 interleave (all layouts natural K-major)
    tohalf_kernel<<<(NTOK*DDIM/4 + 255)/256, 256>>>(x, hx, NTOK*DDIM/4);
    int we4 = NEXP*DDIM*HDIM/4;
    interleave_kernel<<<(we4 + 255)/256, 256>>>(ew1, ew3, wg, we4);
    tohalf_kernel<<<(we4 + 255)/256, 256>>>(ew2, w2h, we4);
    int ws4 = 2*DDIM*HDIM/4;
    interleave_kernel<<<(ws4 + 255)/256, 256>>>(sw1, sw3, swg, ws4);
    tohalf_kernel<<<(ws4 + 255)/256, 256>>>(sw2, sw2h, ws4);

    // routing (exact fp32)
    gate_kernel<<<NTOK / 8, 256>>>(x, gw, gb, topi, wts);
    assign_kernel<<<(NTOK * 2 + 255) / 256, 256>>>(topi, wts, cnt, tokl, wl);
    select_kernel<<<NEXP, 256>>>(cnt, tokl, wl, topi, ktok, kw, mk, pos);

    // ---- shared experts ----
    // fused up: act[NTOK][2H] K-concat (z = col offset HDIM); N = 4096 interleaved
    gemm_h<5,false><<<dim3(2*HDIM/BN, NTOK/BM, 2), 256, SMEM_BYTES>>>(
        hx, 0, DDIM, swg, (size_t)DDIM*2*HDIM, act, (size_t)HDIM, 2*HDIM,
        nullptr, NTOK, 2*HDIM, DDIM, nullptr, nullptr, 1.f);
    // both shared down-projs as ONE K=4096 GEMM; writes ALL of out (fp32)
    gemm_h<2,false><<<dim3(DDIM/BN, NTOK/BM, 1), 256, SMEM_BYTES>>>(
        act, 0, 2*HDIM, sw2h, 0, out, 0, DDIM,
        nullptr, NTOK, DDIM, 2*HDIM, nullptr, nullptr, 0.5f);

    // ---- routed experts ----
    gemm_h<5,true><<<dim3(2*HDIM/BN, (CAP+BM-1)/BM, NEXP), 256, SMEM_BYTES>>>(
        hx, 0, DDIM, wg, (size_t)DDIM*2*HDIM, act, (size_t)CAP*HDIM, HDIM,
        mk, CAP, 2*HDIM, DDIM, ktok, nullptr, 1.f);
    gemm_h<3,false><<<dim3(DDIM/BN, (CAP+BM-1)/BM, NEXP), 256, SMEM_BYTES>>>(
        act, (size_t)CAP*HDIM, HDIM, w2h, (size_t)HDIM*DDIM, yb, (size_t)CAP*DDIM, DDIM,
        nullptr, CAP, DDIM, HDIM, nullptr, kw, 1.f);

    // final gather-sum (no atomics)
    combine_kernel<<<NTOK * 256 / 256, 256>>>(pos, yb, out);
}